// round 8
// baseline (speedup 1.0000x reference)
#include <cuda_runtime.h>
#include <cuda_fp16.h>
#include <math.h>
#include <stdint.h>

#define BB 64      // batch
#define TT 512     // seq len
#define DD 512     // input size
#define HH 1024    // hidden size
#define GG 4096    // 4*H

// ---------------------------------------------------------------------------
// Global scratch
// ---------------------------------------------------------------------------
__device__ float g_xz[(size_t)2 * TT * BB * GG];
__device__ uint2 g_Wfrag[(size_t)2 * 2 * 512 * 64 * 32];
__device__ uint2 g_Wxfrag[(size_t)2 * 2 * 512 * 32 * 32];
__device__ float g_biasp[2 * GG];
__device__ __half g_Xh[(size_t)32768 * 512];
__device__ __half g_Xl[(size_t)32768 * 512];
// h fp16 split: [parity][dir][mat][kc64(16)][b(64)][64 halfs = 128B]
__device__ __align__(16) char g_A[(size_t)2 * 2 * 2 * 16 * 64 * 128];
__device__ unsigned g_barrier;

#define A_MAT ((size_t)16 * 64 * 128)

// smem layout (persistent kernel, per 256-thread CTA)
#define SM_BUF   36864                    // one buffer: 2kh x 2mat x 64 x 144B
#define SM_SRED  (2 * SM_BUF)             // 73728 (+8192)
#define SM_SH    (SM_SRED + 8192)         // 81920 (+2304)
#define SM_TOTAL (SM_SH + 64 * 9 * 4)     // 84224

// ---------------------------------------------------------------------------
#define MMA16816(d, a0, a1, a2, a3, b0, b1)                                  \
    asm volatile(                                                            \
        "mma.sync.aligned.m16n8k16.row.col.f32.f16.f16.f32 "                 \
        "{%0,%1,%2,%3}, {%4,%5,%6,%7}, {%8,%9}, {%0,%1,%2,%3};"              \
        : "+f"((d)[0]), "+f"((d)[1]), "+f"((d)[2]), "+f"((d)[3])             \
        : "r"(a0), "r"(a1), "r"(a2), "r"(a3), "r"(b0), "r"(b1))

#define LDSM_X4(r0, r1, r2, r3, addr)                                        \
    asm volatile(                                                            \
        "ldmatrix.sync.aligned.m8n8.x4.shared.b16 {%0,%1,%2,%3}, [%4];"      \
        : "=r"(r0), "=r"(r1), "=r"(r2), "=r"(r3) : "r"(addr))

#define CP16(dst, src)                                                       \
    asm volatile("cp.async.cg.shared.global [%0], [%1], 16;"                 \
                 :: "r"(dst), "l"(src))

__device__ __forceinline__ uint32_t smem_u32(const void* p) {
    uint32_t a;
    asm("{ .reg .u64 t; cvta.to.shared.u64 t, %1; cvt.u32.u64 %0, t; }"
        : "=r"(a) : "l"(p));
    return a;
}

// ---------------------------------------------------------------------------
__global__ void init_kernel() {
    int i = blockIdx.x * blockDim.x + threadIdx.x;   // 0..262143
    ((uint32_t*)g_A)[i] = 0u;
    if (i == 0) g_barrier = 0u;
}

// ---------------------------------------------------------------------------
__global__ void convX_kernel(const float* __restrict__ X) {
    size_t idx = (size_t)blockIdx.x * blockDim.x + threadIdx.x;
    float4 v = ((const float4*)X)[idx];
    __half h0 = __float2half_rn(v.x), h1 = __float2half_rn(v.y);
    __half h2 = __float2half_rn(v.z), h3 = __float2half_rn(v.w);
    uint2 hi, lo;
    hi.x = (uint32_t)__half_as_ushort(h0) | ((uint32_t)__half_as_ushort(h1) << 16);
    hi.y = (uint32_t)__half_as_ushort(h2) | ((uint32_t)__half_as_ushort(h3) << 16);
    __half l0 = __float2half_rn(v.x - __half2float(h0));
    __half l1 = __float2half_rn(v.y - __half2float(h1));
    __half l2 = __float2half_rn(v.z - __half2float(h2));
    __half l3 = __float2half_rn(v.w - __half2float(h3));
    lo.x = (uint32_t)__half_as_ushort(l0) | ((uint32_t)__half_as_ushort(l1) << 16);
    lo.y = (uint32_t)__half_as_ushort(l2) | ((uint32_t)__half_as_ushort(l3) << 16);
    ((uint2*)g_Xh)[idx] = hi;
    ((uint2*)g_Xl)[idx] = lo;
}

// ---------------------------------------------------------------------------
__global__ void convW_kernel(const float* __restrict__ Whf,
                             const float* __restrict__ Whb) {
    int idx = blockIdx.x * blockDim.x + threadIdx.x;
    int lane = idx & 31;
    int kc   = (idx >> 5) & 63;
    int nt   = (idx >> 11) & 511;
    int dir  = idx >> 20;
    const float* W = dir ? Whb : Whf;

    int p   = nt * 8 + (lane >> 2);
    int col = ((p & 3) << 10) + (p >> 2);
    int k0  = kc * 16 + (lane & 3) * 2;

    float w0 = W[(size_t)(k0)     * GG + col];
    float w1 = W[(size_t)(k0 + 1) * GG + col];
    float w2 = W[(size_t)(k0 + 8) * GG + col];
    float w3 = W[(size_t)(k0 + 9) * GG + col];

    __half h0 = __float2half_rn(w0), h1 = __float2half_rn(w1);
    __half h2 = __float2half_rn(w2), h3 = __float2half_rn(w3);
    uint2 hi, lo;
    hi.x = (uint32_t)__half_as_ushort(h0) | ((uint32_t)__half_as_ushort(h1) << 16);
    hi.y = (uint32_t)__half_as_ushort(h2) | ((uint32_t)__half_as_ushort(h3) << 16);
    lo.x = (uint32_t)__half_as_ushort(__float2half_rn(w0 - __half2float(h0))) |
           ((uint32_t)__half_as_ushort(__float2half_rn(w1 - __half2float(h1))) << 16);
    lo.y = (uint32_t)__half_as_ushort(__float2half_rn(w2 - __half2float(h2))) |
           ((uint32_t)__half_as_ushort(__float2half_rn(w3 - __half2float(h3))) << 16);

    g_Wfrag[((((size_t)dir * 2 + 0) * 512 + nt) * 64 + kc) * 32 + lane] = hi;
    g_Wfrag[((((size_t)dir * 2 + 1) * 512 + nt) * 64 + kc) * 32 + lane] = lo;
}

// ---------------------------------------------------------------------------
__global__ void convWx_kernel(const float* __restrict__ Wxf,
                              const float* __restrict__ Wxb,
                              const float* __restrict__ bf,
                              const float* __restrict__ bb) {
    int idx = blockIdx.x * blockDim.x + threadIdx.x;
    int lane = idx & 31;
    int kc   = (idx >> 5) & 31;
    int nt   = (idx >> 10) & 511;
    int dir  = idx >> 19;
    const float* W = dir ? Wxb : Wxf;

    int p   = nt * 8 + (lane >> 2);
    int col = ((p & 3) << 10) + (p >> 2);
    int k0  = kc * 16 + (lane & 3) * 2;

    float w0 = W[(size_t)(k0)     * GG + col];
    float w1 = W[(size_t)(k0 + 1) * GG + col];
    float w2 = W[(size_t)(k0 + 8) * GG + col];
    float w3 = W[(size_t)(k0 + 9) * GG + col];

    __half h0 = __float2half_rn(w0), h1 = __float2half_rn(w1);
    __half h2 = __float2half_rn(w2), h3 = __float2half_rn(w3);
    uint2 hi, lo;
    hi.x = (uint32_t)__half_as_ushort(h0) | ((uint32_t)__half_as_ushort(h1) << 16);
    hi.y = (uint32_t)__half_as_ushort(h2) | ((uint32_t)__half_as_ushort(h3) << 16);
    lo.x = (uint32_t)__half_as_ushort(__float2half_rn(w0 - __half2float(h0))) |
           ((uint32_t)__half_as_ushort(__float2half_rn(w1 - __half2float(h1))) << 16);
    lo.y = (uint32_t)__half_as_ushort(__float2half_rn(w2 - __half2float(h2))) |
           ((uint32_t)__half_as_ushort(__float2half_rn(w3 - __half2float(h3))) << 16);

    g_Wxfrag[((((size_t)dir * 2 + 0) * 512 + nt) * 32 + kc) * 32 + lane] = hi;
    g_Wxfrag[((((size_t)dir * 2 + 1) * 512 + nt) * 32 + kc) * 32 + lane] = lo;

    if (kc == 0 && (lane & 3) == 0) {
        const float* bias = dir ? bb : bf;
        g_biasp[dir * GG + p] = bias[col];
    }
}

// ---------------------------------------------------------------------------
// Input projection (unchanged)
// ---------------------------------------------------------------------------
__global__ void __launch_bounds__(256, 1) proj_kernel() {
    __shared__ __align__(16) char sX[2 * 12288];

    const int dir = blockIdx.z;
    const int n0 = blockIdx.x * 128;
    const int m0 = blockIdx.y * 128;
    const int tid = threadIdx.x;
    const int warp = tid >> 5, lane = tid & 31;
    const int wm = warp >> 2, wn = warp & 3;
    const int qr = lane >> 2, qc = lane & 3;

    const size_t MATSTRIDE = (size_t)512 * 32 * 32;
    const uint2* WX = g_Wxfrag + (size_t)dir * 2 * MATSTRIDE;
    const int ntbase = (n0 >> 3) + wn * 4;

    const uint32_t sX0 = smem_u32(sX);

    auto stage = [&](int c) {
#pragma unroll
        for (int r = 0; r < 2; r++) {
            const int idx = tid + r * 256;
            const int mat = idx >> 8, row = (idx >> 1) & 127, q = idx & 1;
            const char* src = (const char*)(mat ? g_Xl : g_Xh) +
                              (((size_t)(m0 + row) * 512 + c * 16) << 1) + q * 16;
            const uint32_t dst = sX0 + (c & 1) * 12288 + mat * 6144 + row * 48 + q * 16;
            CP16(dst, src);
        }
    };

    float d[4][4][4] = {};

    stage(0);
    asm volatile("cp.async.commit_group;" ::: "memory");

    for (int c = 0; c < 32; c++) {
        __syncthreads();
        if (c < 31) {
            stage(c + 1);
            asm volatile("cp.async.commit_group;" ::: "memory");
            asm volatile("cp.async.wait_group 1;" ::: "memory");
        } else {
            asm volatile("cp.async.wait_group 0;" ::: "memory");
        }
        __syncthreads();

        uint2 bh[4], bl[4];
#pragma unroll
        for (int nt = 0; nt < 4; nt++) {
            const size_t off = (((size_t)(ntbase + nt)) * 32 + c) * 32 + lane;
            bh[nt] = WX[off];
            bl[nt] = WX[off + MATSTRIDE];
        }

        const uint32_t slot = sX0 + (c & 1) * 12288;
        const uint32_t lrow = (lane & 15) * 48 + ((lane >> 4) << 4);
#pragma unroll
        for (int mt = 0; mt < 4; mt++) {
            const uint32_t arow = slot + (wm * 64 + mt * 16) * 48 + lrow;
            uint32_t a0, a1, a2, a3, l0, l1, l2, l3;
            LDSM_X4(a0, a1, a2, a3, arow);
            LDSM_X4(l0, l1, l2, l3, arow + 6144);
#pragma unroll
            for (int nt = 0; nt < 4; nt++) {
                MMA16816(d[mt][nt], a0, a1, a2, a3, bh[nt].x, bh[nt].y);
                MMA16816(d[mt][nt], a0, a1, a2, a3, bl[nt].x, bl[nt].y);
                MMA16816(d[mt][nt], l0, l1, l2, l3, bh[nt].x, bh[nt].y);
            }
        }
    }

#pragma unroll
    for (int mt = 0; mt < 4; mt++) {
#pragma unroll
        for (int nt = 0; nt < 4; nt++) {
            const int n = n0 + wn * 32 + nt * 8 + qc * 2;
            const float2 bv = *(const float2*)(g_biasp + dir * GG + n);
            const int ma = m0 + wm * 64 + mt * 16 + qr;
            const int mb = ma + 8;
            float2 v0, v1;
            v0.x = d[mt][nt][0] + bv.x; v0.y = d[mt][nt][1] + bv.y;
            v1.x = d[mt][nt][2] + bv.x; v1.y = d[mt][nt][3] + bv.y;
            *(float2*)(g_xz + (((size_t)dir * TT + (ma & 511)) * BB + (ma >> 9)) * GG + n) = v0;
            *(float2*)(g_xz + (((size_t)dir * TT + (mb & 511)) * BB + (mb >> 9)) * GG + n) = v1;
        }
    }
}

// ---------------------------------------------------------------------------
// Persistent recurrence: grid (128, 2) = 256 CTAs x 256 threads (2 CTAs/SM).
// CTA = 4 ntiles (8 hidden units) x 2 kh halves; two-buffer cp.async pipeline;
// independent CTAs on one SM overlap each other's sync convoys.
// ---------------------------------------------------------------------------
__global__ void __launch_bounds__(256, 2) lstm_kernel(float* __restrict__ out) {
    extern __shared__ char dsm[];
    const uint32_t sA0 = smem_u32(dsm);
    float* sred = (float*)(dsm + SM_SRED);         // [2kh][4ntw][8][32]
    float (*sh)[9] = (float(*)[9])(dsm + SM_SH);   // [64][9]

    const int dir = blockIdx.y;
    const int nb  = blockIdx.x;                    // 0..127
    const int tid  = threadIdx.x;
    const int warp = tid >> 5;                     // 0..7
    const int lane = tid & 31;
    const int ntw = warp & 3;
    const int kh  = warp >> 2;
    const int qr = lane >> 2;
    const int qc = lane & 3;
    const int ntg = nb * 4 + ntw;

    const uint2* Bh = g_Wfrag + (((size_t)(dir * 2 + 0) * 512 + ntg) * 64) * 32 + lane;
    const uint2* Bl = g_Wfrag + (((size_t)(dir * 2 + 1) * 512 + ntg) * 64) * 32 + lane;

    const int u = qc >> 1;
    const int j = nb * 8 + ntw * 2 + u;            // hidden unit index
    const bool odd = qc & 1;
    const int lu = ntw * 2 + u;                    // unit within CTA (0..7)
    const int mtlo = kh * 2;                       // this warp's epilogue mt pair

    float cv[2] = {0.0f, 0.0f};

    // initial xz prefetch (step 0)
    float4 xv[2];
    {
        const int t0 = dir ? (TT - 1) : 0;
        const float* xz = g_xz + ((size_t)dir * TT + t0) * BB * GG;
#pragma unroll
        for (int q = 0; q < 2; q++) {
            const int b = (mtlo + q) * 16 + qr + (odd ? 8 : 0);
            xv[q] = *(const float4*)(xz + (size_t)b * GG + j * 4);
        }
    }

    for (int s = 0; s < TT; s++) {
        const int t  = dir ? (TT - 1 - s) : s;
        const int pr = s & 1;
        const int pw = pr ^ 1;
        const char* srcA = g_A + (size_t)(pr * 2 + dir) * 2 * A_MAT;

        // stage chunk c (kc64) for both kh halves, both mats: 32KB -> buffer c&1
        auto stage = [&](int c) {
            const uint32_t bufo = (uint32_t)(c & 1) * SM_BUF;
#pragma unroll
            for (int r = 0; r < 8; r++) {
                const int idx = tid + r * 256;
                const int khs = idx >> 10;
                const int m = (idx >> 9) & 1;
                const int b = (idx >> 3) & 63;
                const int q = idx & 7;
                const char* src = srcA + (size_t)m * A_MAT +
                                  ((size_t)((khs * 8 + c) * 64 + b)) * 128 + q * 16;
                const uint32_t dst = sA0 + bufo + khs * 18432 +
                                     m * 9216 + b * 144 + q * 16;
                CP16(dst, src);
            }
        };

        float d[4][4] = {};

        stage(0);
        asm volatile("cp.async.commit_group;" ::: "memory");

        for (int c = 0; c < 8; c++) {
            uint2 wh[4], wl[4];
#pragma unroll
            for (int sub = 0; sub < 4; sub++) {
                const size_t off = (size_t)((kh * 32 + c * 4 + sub)) * 32;
                wh[sub] = Bh[off];
                wl[sub] = Bl[off];
            }
            __syncthreads();            // compute(c-1) done: other buffer free
            if (c < 7) {
                stage(c + 1);
                asm volatile("cp.async.commit_group;" ::: "memory");
                asm volatile("cp.async.wait_group 1;" ::: "memory");
            } else {
                asm volatile("cp.async.wait_group 0;" ::: "memory");
            }
            __syncthreads();            // chunk c visible

            const uint32_t slot = sA0 + (uint32_t)(c & 1) * SM_BUF + kh * 18432;
            const uint32_t lrow = (lane & 15) * 144 + ((lane >> 4) << 4);
#pragma unroll
            for (int sub = 0; sub < 4; sub++) {
                const uint32_t arow = slot + sub * 32 + lrow;
#pragma unroll
                for (int mt = 0; mt < 4; mt++) {
                    uint32_t a0, a1, a2, a3, l0, l1, l2, l3;
                    LDSM_X4(a0, a1, a2, a3, arow + mt * 2304);
                    LDSM_X4(l0, l1, l2, l3, arow + mt * 2304 + 9216);
                    MMA16816(d[mt], a0, a1, a2, a3, wh[sub].x, wh[sub].y);
                    MMA16816(d[mt], a0, a1, a2, a3, wl[sub].x, wl[sub].y);
                    MMA16816(d[mt], l0, l1, l2, l3, wh[sub].x, wh[sub].y);
                }
            }
        }

        // --- partial exchange: each kh group exports the other's mt pair ---
        {
            const int omt = 2 - mtlo;
#pragma unroll
            for (int q = 0; q < 2; q++)
#pragma unroll
                for (int e = 0; e < 4; e++)
                    sred[(((kh * 4 + ntw) * 8) + q * 4 + e) * 32 + lane] = d[omt + q][e];
        }
        __syncthreads();

        // --- add partials + gate math for this warp's mt pair ---
        {
            const int okh = kh ^ 1;
#pragma unroll
            for (int q = 0; q < 2; q++) {
#pragma unroll
                for (int e = 0; e < 4; e++)
                    d[mtlo + q][e] += sred[(((okh * 4 + ntw) * 8) + q * 4 + e) * 32 + lane];

                float* dd = d[mtlo + q];
                float e0 = __shfl_xor_sync(0xffffffffu, dd[0], 1);
                float e1 = __shfl_xor_sync(0xffffffffu, dd[1], 1);
                float e2 = __shfl_xor_sync(0xffffffffu, dd[2], 1);
                float e3 = __shfl_xor_sync(0xffffffffu, dd[3], 1);
                const int b = (mtlo + q) * 16 + qr + (odd ? 8 : 0);

                float zi = odd ? e2 : dd[0];
                float zf = odd ? e3 : dd[1];
                float zo = odd ? dd[2] : e0;
                float zg = odd ? dd[3] : e1;

                zi += xv[q].x; zf += xv[q].y; zo += xv[q].z; zg += xv[q].w;

                const float ig = 1.0f / (1.0f + __expf(-zi));
                const float fg = 1.0f / (1.0f + __expf(-zf));
                const float og = 1.0f / (1.0f + __expf(-zo));
                const float gt = tanhf(zg);

                const float cn = fg * cv[q] + ig * gt;
                const float hn = og * tanhf(cn);
                cv[q] = cn;
                sh[b][lu] = hn;
            }
        }
        __syncthreads();

        // --- write h (hi/lo fp16) for next step, parity pw ---
        if (tid < 128) {
            const int b = tid & 63;
            const int mat = tid >> 6;
            char* dst = g_A + ((size_t)(pw * 2 + dir) * 2 + mat) * A_MAT +
                        ((size_t)((nb >> 3) * 64 + b)) * 128 + (nb & 7) * 16;
            __half tmp[8];
#pragma unroll
            for (int q = 0; q < 8; q++) {
                float h = sh[b][q];
                __half hh = __float2half_rn(h);
                tmp[q] = mat ? __float2half_rn(h - __half2float(hh)) : hh;
            }
            *(uint4*)(dst) = *(uint4*)(tmp);
        }

        // --- coalesced out store: 32B runs per (b, t) ---
        {
            const int b = tid >> 2;
            const int e = tid & 3;
            float2 v;
            v.x = sh[b][e * 2];
            v.y = sh[b][e * 2 + 1];
            *(float2*)(out + (((size_t)b * TT + t) * 2 + dir) * HH +
                       nb * 8 + e * 2) = v;
        }

        // --- grid barrier + next-step xz prefetch during spin ---
        if (s < TT - 1) {
            __syncthreads();
            if (tid == 0) {
                asm volatile("red.release.gpu.global.add.u32 [%0], 1;"
                             :: "l"(&g_barrier) : "memory");
            }
            {   // prefetch xz(s+1): independent of barrier
                const int tn = dir ? (TT - 2 - s) : (s + 1);
                const float* xz = g_xz + ((size_t)dir * TT + tn) * BB * GG;
#pragma unroll
                for (int q = 0; q < 2; q++) {
                    const int b = (mtlo + q) * 16 + qr + (odd ? 8 : 0);
                    xv[q] = *(const float4*)(xz + (size_t)b * GG + j * 4);
                }
            }
            if (tid == 0) {
                const unsigned target = 256u * (unsigned)(s + 1);
                unsigned v;
                do {
                    asm volatile("ld.acquire.gpu.global.u32 %0, [%1];"
                                 : "=r"(v) : "l"(&g_barrier) : "memory");
                } while (v < target);
            }
            __syncthreads();
        }
    }
}

// ---------------------------------------------------------------------------
extern "C" void kernel_launch(void* const* d_in, const int* in_sizes, int n_in,
                              void* d_out, int out_size) {
    const float* X    = (const float*)d_in[0];
    const float* Wx_f = (const float*)d_in[1];
    const float* Wh_f = (const float*)d_in[2];
    const float* b_f  = (const float*)d_in[3];
    const float* Wx_b = (const float*)d_in[4];
    const float* Wh_b = (const float*)d_in[5];
    const float* b_b  = (const float*)d_in[6];
    float* out = (float*)d_out;

    cudaFuncSetAttribute(lstm_kernel,
                         cudaFuncAttributeMaxDynamicSharedMemorySize, SM_TOTAL);

    init_kernel<<<1024, 256>>>();
    convX_kernel<<<16384, 256>>>(X);
    convW_kernel<<<8192, 256>>>(Wh_f, Wh_b);
    convWx_kernel<<<4096, 256>>>(Wx_f, Wx_b, b_f, b_b);

    proj_kernel<<<dim3(32, 256, 2), 256>>>();

    lstm_kernel<<<dim3(128, 2), 256, SM_TOTAL>>>(out);
}

// round 9
// speedup vs baseline: 2.0923x; 2.0923x over previous
#include <cuda_runtime.h>
#include <cuda_fp16.h>
#include <math.h>
#include <stdint.h>

#define BB 64      // batch
#define TT 512     // seq len
#define DD 512     // input size
#define HH 1024    // hidden size
#define GG 4096    // 4*H

// ---------------------------------------------------------------------------
// Global scratch
// ---------------------------------------------------------------------------
__device__ float g_xz[(size_t)2 * TT * BB * GG];
// Wh fp16 split (B side keeps hi+lo): [dir][mat][nt(512)][kc16(64)][lane(32)]
__device__ uint2 g_Wfrag[(size_t)2 * 2 * 512 * 64 * 32];
__device__ uint2 g_Wxfrag[(size_t)2 * 2 * 512 * 32 * 32];
__device__ float g_biasp[2 * GG];
// X fp16 (hi only): [m(32768)][k(512)]
__device__ __half g_Xh[(size_t)32768 * 512];
// h fp16 (hi only): [parity][dir][kc64(16)][b(64)][64 halfs = 128B]
__device__ __align__(16) char g_A[(size_t)2 * 2 * 16 * 64 * 128];
__device__ unsigned g_barrier;

#define A_PD ((size_t)16 * 64 * 128)   // 131072 B per (parity,dir)

// smem layout (lstm kernel): 16 chunks x (64 rows x 144B) + sred + sh
#define SM_SRED  147456
#define SM_SH    (SM_SRED + 16384)        // 163840
#define SM_TOTAL (SM_SH + 64 * 17 * 4)    // 168192

// ---------------------------------------------------------------------------
#define MMA16816(d, a0, a1, a2, a3, b0, b1)                                  \
    asm volatile(                                                            \
        "mma.sync.aligned.m16n8k16.row.col.f32.f16.f16.f32 "                 \
        "{%0,%1,%2,%3}, {%4,%5,%6,%7}, {%8,%9}, {%0,%1,%2,%3};"              \
        : "+f"((d)[0]), "+f"((d)[1]), "+f"((d)[2]), "+f"((d)[3])             \
        : "r"(a0), "r"(a1), "r"(a2), "r"(a3), "r"(b0), "r"(b1))

#define LDSM_X4(r0, r1, r2, r3, addr)                                        \
    asm volatile(                                                            \
        "ldmatrix.sync.aligned.m8n8.x4.shared.b16 {%0,%1,%2,%3}, [%4];"      \
        : "=r"(r0), "=r"(r1), "=r"(r2), "=r"(r3) : "r"(addr))

#define CP16(dst, src)                                                       \
    asm volatile("cp.async.cg.shared.global [%0], [%1], 16;"                 \
                 :: "r"(dst), "l"(src))

__device__ __forceinline__ uint32_t smem_u32(const void* p) {
    uint32_t a;
    asm("{ .reg .u64 t; cvta.to.shared.u64 t, %1; cvt.u32.u64 %0, t; }"
        : "=r"(a) : "l"(p));
    return a;
}

// ---------------------------------------------------------------------------
__global__ void init_kernel() {
    int i = blockIdx.x * blockDim.x + threadIdx.x;   // 0..131071
    ((uint32_t*)g_A)[i] = 0u;                        // all 512KB of g_A
    if (i == 0) g_barrier = 0u;
}

// ---------------------------------------------------------------------------
__global__ void convX_kernel(const float* __restrict__ X) {
    size_t idx = (size_t)blockIdx.x * blockDim.x + threadIdx.x;
    float4 v = ((const float4*)X)[idx];
    __half h0 = __float2half_rn(v.x), h1 = __float2half_rn(v.y);
    __half h2 = __float2half_rn(v.z), h3 = __float2half_rn(v.w);
    uint2 hi;
    hi.x = (uint32_t)__half_as_ushort(h0) | ((uint32_t)__half_as_ushort(h1) << 16);
    hi.y = (uint32_t)__half_as_ushort(h2) | ((uint32_t)__half_as_ushort(h3) << 16);
    ((uint2*)g_Xh)[idx] = hi;
}

// ---------------------------------------------------------------------------
__global__ void convW_kernel(const float* __restrict__ Whf,
                             const float* __restrict__ Whb) {
    int idx = blockIdx.x * blockDim.x + threadIdx.x;
    int lane = idx & 31;
    int kc   = (idx >> 5) & 63;
    int nt   = (idx >> 11) & 511;
    int dir  = idx >> 20;
    const float* W = dir ? Whb : Whf;

    int p   = nt * 8 + (lane >> 2);
    int col = ((p & 3) << 10) + (p >> 2);
    int k0  = kc * 16 + (lane & 3) * 2;

    float w0 = W[(size_t)(k0)     * GG + col];
    float w1 = W[(size_t)(k0 + 1) * GG + col];
    float w2 = W[(size_t)(k0 + 8) * GG + col];
    float w3 = W[(size_t)(k0 + 9) * GG + col];

    __half h0 = __float2half_rn(w0), h1 = __float2half_rn(w1);
    __half h2 = __float2half_rn(w2), h3 = __float2half_rn(w3);
    uint2 hi, lo;
    hi.x = (uint32_t)__half_as_ushort(h0) | ((uint32_t)__half_as_ushort(h1) << 16);
    hi.y = (uint32_t)__half_as_ushort(h2) | ((uint32_t)__half_as_ushort(h3) << 16);
    lo.x = (uint32_t)__half_as_ushort(__float2half_rn(w0 - __half2float(h0))) |
           ((uint32_t)__half_as_ushort(__float2half_rn(w1 - __half2float(h1))) << 16);
    lo.y = (uint32_t)__half_as_ushort(__float2half_rn(w2 - __half2float(h2))) |
           ((uint32_t)__half_as_ushort(__float2half_rn(w3 - __half2float(h3))) << 16);

    g_Wfrag[((((size_t)dir * 2 + 0) * 512 + nt) * 64 + kc) * 32 + lane] = hi;
    g_Wfrag[((((size_t)dir * 2 + 1) * 512 + nt) * 64 + kc) * 32 + lane] = lo;
}

// ---------------------------------------------------------------------------
__global__ void convWx_kernel(const float* __restrict__ Wxf,
                              const float* __restrict__ Wxb,
                              const float* __restrict__ bf,
                              const float* __restrict__ bb) {
    int idx = blockIdx.x * blockDim.x + threadIdx.x;
    int lane = idx & 31;
    int kc   = (idx >> 5) & 31;
    int nt   = (idx >> 10) & 511;
    int dir  = idx >> 19;
    const float* W = dir ? Wxb : Wxf;

    int p   = nt * 8 + (lane >> 2);
    int col = ((p & 3) << 10) + (p >> 2);
    int k0  = kc * 16 + (lane & 3) * 2;

    float w0 = W[(size_t)(k0)     * GG + col];
    float w1 = W[(size_t)(k0 + 1) * GG + col];
    float w2 = W[(size_t)(k0 + 8) * GG + col];
    float w3 = W[(size_t)(k0 + 9) * GG + col];

    __half h0 = __float2half_rn(w0), h1 = __float2half_rn(w1);
    __half h2 = __float2half_rn(w2), h3 = __float2half_rn(w3);
    uint2 hi, lo;
    hi.x = (uint32_t)__half_as_ushort(h0) | ((uint32_t)__half_as_ushort(h1) << 16);
    hi.y = (uint32_t)__half_as_ushort(h2) | ((uint32_t)__half_as_ushort(h3) << 16);
    lo.x = (uint32_t)__half_as_ushort(__float2half_rn(w0 - __half2float(h0))) |
           ((uint32_t)__half_as_ushort(__float2half_rn(w1 - __half2float(h1))) << 16);
    lo.y = (uint32_t)__half_as_ushort(__float2half_rn(w2 - __half2float(h2))) |
           ((uint32_t)__half_as_ushort(__float2half_rn(w3 - __half2float(h3))) << 16);

    g_Wxfrag[((((size_t)dir * 2 + 0) * 512 + nt) * 32 + kc) * 32 + lane] = hi;
    g_Wxfrag[((((size_t)dir * 2 + 1) * 512 + nt) * 32 + kc) * 32 + lane] = lo;

    if (kc == 0 && (lane & 3) == 0) {
        const float* bias = dir ? bb : bf;
        g_biasp[dir * GG + p] = bias[col];
    }
}

// ---------------------------------------------------------------------------
// Input projection: 2-term split (X_hi * (W_hi + W_lo)).
// ---------------------------------------------------------------------------
__global__ void __launch_bounds__(256, 1) proj_kernel() {
    __shared__ __align__(16) char sX[2 * 6144];   // 2 buf x 128 rows x 48B

    const int dir = blockIdx.z;
    const int n0 = blockIdx.x * 128;
    const int m0 = blockIdx.y * 128;
    const int tid = threadIdx.x;
    const int warp = tid >> 5, lane = tid & 31;
    const int wm = warp >> 2, wn = warp & 3;
    const int qr = lane >> 2, qc = lane & 3;

    const size_t MATSTRIDE = (size_t)512 * 32 * 32;
    const uint2* WX = g_Wxfrag + (size_t)dir * 2 * MATSTRIDE;
    const int ntbase = (n0 >> 3) + wn * 4;

    const uint32_t sX0 = smem_u32(sX);

    auto stage = [&](int c) {
        const int row = tid >> 1, q = tid & 1;
        const char* src = (const char*)g_Xh +
                          (((size_t)(m0 + row) * 512 + c * 16) << 1) + q * 16;
        const uint32_t dst = sX0 + (c & 1) * 6144 + row * 48 + q * 16;
        CP16(dst, src);
    };

    float d[4][4][4] = {};

    stage(0);
    asm volatile("cp.async.commit_group;" ::: "memory");

    for (int c = 0; c < 32; c++) {
        __syncthreads();
        if (c < 31) {
            stage(c + 1);
            asm volatile("cp.async.commit_group;" ::: "memory");
            asm volatile("cp.async.wait_group 1;" ::: "memory");
        } else {
            asm volatile("cp.async.wait_group 0;" ::: "memory");
        }
        __syncthreads();

        uint2 bh[4], bl[4];
#pragma unroll
        for (int nt = 0; nt < 4; nt++) {
            const size_t off = (((size_t)(ntbase + nt)) * 32 + c) * 32 + lane;
            bh[nt] = WX[off];
            bl[nt] = WX[off + MATSTRIDE];
        }

        const uint32_t slot = sX0 + (c & 1) * 6144;
        const uint32_t lrow = (lane & 15) * 48 + ((lane >> 4) << 4);
#pragma unroll
        for (int mt = 0; mt < 4; mt++) {
            const uint32_t arow = slot + (wm * 64 + mt * 16) * 48 + lrow;
            uint32_t a0, a1, a2, a3;
            LDSM_X4(a0, a1, a2, a3, arow);
#pragma unroll
            for (int nt = 0; nt < 4; nt++) {
                MMA16816(d[mt][nt], a0, a1, a2, a3, bh[nt].x, bh[nt].y);
                MMA16816(d[mt][nt], a0, a1, a2, a3, bl[nt].x, bl[nt].y);
            }
        }
    }

#pragma unroll
    for (int mt = 0; mt < 4; mt++) {
#pragma unroll
        for (int nt = 0; nt < 4; nt++) {
            const int n = n0 + wn * 32 + nt * 8 + qc * 2;
            const float2 bv = *(const float2*)(g_biasp + dir * GG + n);
            const int ma = m0 + wm * 64 + mt * 16 + qr;
            const int mb = ma + 8;
            float2 v0, v1;
            v0.x = d[mt][nt][0] + bv.x; v0.y = d[mt][nt][1] + bv.y;
            v1.x = d[mt][nt][2] + bv.x; v1.y = d[mt][nt][3] + bv.y;
            *(float2*)(g_xz + (((size_t)dir * TT + (ma & 511)) * BB + (ma >> 9)) * GG + n) = v0;
            *(float2*)(g_xz + (((size_t)dir * TT + (mb & 511)) * BB + (mb >> 9)) * GG + n) = v1;
        }
    }
}

// ---------------------------------------------------------------------------
// Persistent recurrence: grid (64,2), 512 threads (8 ntiles x 2 kh).
// 2-term split; full A_hi staged into smem once per step (2 convoys).
// ---------------------------------------------------------------------------
__global__ void __launch_bounds__(512, 1) lstm_kernel(float* __restrict__ out) {
    extern __shared__ char dsm[];
    const uint32_t sA0 = smem_u32(dsm);               // 16 chunks x 64 x 144B
    float* sred = (float*)(dsm + SM_SRED);            // [2kh][8ntw][8][32]
    float (*sh)[17] = (float(*)[17])(dsm + SM_SH);    // [64][17]

    const int dir  = blockIdx.y;
    const int nblk = blockIdx.x;                      // 0..63
    const int tid  = threadIdx.x;
    const int warp = tid >> 5;
    const int lane = tid & 31;
    const int ntw = warp & 7;
    const int kh  = warp >> 3;
    const int qr = lane >> 2;
    const int qc = lane & 3;
    const int ntg = nblk * 8 + ntw;

    const uint2* Bh = g_Wfrag + (((size_t)(dir * 2 + 0) * 512 + ntg) * 64) * 32 + lane;
    const uint2* Bl = g_Wfrag + (((size_t)(dir * 2 + 1) * 512 + ntg) * 64) * 32 + lane;

    const int u = qc >> 1;
    const int j = nblk * 16 + ntw * 2 + u;
    const bool odd = qc & 1;
    const int lu = ntw * 2 + u;
    const int mtlo = kh * 2;                          // this warp's epilogue mt pair

    // stage decode (constant per thread): each r covers one chunk (512 ops)
    const int st_b = tid >> 3;
    const int st_q = tid & 7;

    float cv[2] = {0.0f, 0.0f};

    float4 xv[2];
    {
        const int t0 = dir ? (TT - 1) : 0;
        const float* xz = g_xz + ((size_t)dir * TT + t0) * BB * GG;
#pragma unroll
        for (int q = 0; q < 2; q++) {
            const int b = (mtlo + q) * 16 + qr + (odd ? 8 : 0);
            xv[q] = *(const float4*)(xz + (size_t)b * GG + j * 4);
        }
    }

    for (int s = 0; s < TT; s++) {
        const int t  = dir ? (TT - 1 - s) : s;
        const int pr = s & 1;
        const int pw = pr ^ 1;
        const char* srcA = g_A + (size_t)(pr * 2 + dir) * A_PD;

        // ---- stage all 16 chunks in 2 groups ----
        // group g covers ci = g*8 + r; chunk order interleaves kh halves:
        // group0 -> chunks {0..3, 8..11}, group1 -> chunks {4..7, 12..15}
#pragma unroll
        for (int g = 0; g < 2; g++) {
#pragma unroll
            for (int r = 0; r < 8; r++) {
                const int ci = g * 8 + r;
                const int chunk = (ci & 3) + (((ci >> 2) & 1) << 3) + ((ci >> 3) << 2);
                const char* src = srcA + (size_t)chunk * 8192 + st_b * 128 + st_q * 16;
                const uint32_t dst = sA0 + chunk * 9216 + st_b * 144 + st_q * 16;
                CP16(dst, src);
            }
            asm volatile("cp.async.commit_group;" ::: "memory");
        }

        float d[4][4] = {};

        // ---- compute: 2 phases x 4 chunks x 4 ksteps ----
#pragma unroll
        for (int phase = 0; phase < 2; phase++) {
            if (phase == 0) {
                asm volatile("cp.async.wait_group 1;" ::: "memory");
            } else {
                asm volatile("cp.async.wait_group 0;" ::: "memory");
            }
            __syncthreads();

#pragma unroll
            for (int cc = 0; cc < 4; cc++) {
                const int chunk = kh * 8 + phase * 4 + cc;
                uint2 wh[4], wl[4];
#pragma unroll
                for (int sub = 0; sub < 4; sub++) {
                    const size_t off = (size_t)(chunk * 4 + sub) * 32;
                    wh[sub] = Bh[off];
                    wl[sub] = Bl[off];
                }
                const uint32_t slot = sA0 + chunk * 9216;
                const uint32_t lrow = (lane & 15) * 144 + ((lane >> 4) << 4);
#pragma unroll
                for (int sub = 0; sub < 4; sub++) {
                    const uint32_t arow = slot + sub * 32 + lrow;
#pragma unroll
                    for (int mt = 0; mt < 4; mt++) {
                        uint32_t a0, a1, a2, a3;
                        LDSM_X4(a0, a1, a2, a3, arow + mt * 2304);
                        MMA16816(d[mt], a0, a1, a2, a3, wh[sub].x, wh[sub].y);
                        MMA16816(d[mt], a0, a1, a2, a3, wl[sub].x, wl[sub].y);
                    }
                }
            }
        }

        // ---- partial exchange: each kh group exports the other's mt pair ----
        {
            const int omt = 2 - mtlo;
#pragma unroll
            for (int q = 0; q < 2; q++)
#pragma unroll
                for (int e = 0; e < 4; e++)
                    sred[(((kh * 8 + ntw) * 8) + q * 4 + e) * 32 + lane] = d[omt + q][e];
        }
        __syncthreads();

        // ---- reduce + gate math for this warp's mt pair ----
        {
            const int okh = kh ^ 1;
#pragma unroll
            for (int q = 0; q < 2; q++) {
#pragma unroll
                for (int e = 0; e < 4; e++)
                    d[mtlo + q][e] += sred[(((okh * 8 + ntw) * 8) + q * 4 + e) * 32 + lane];

                float* dd = d[mtlo + q];
                float e0 = __shfl_xor_sync(0xffffffffu, dd[0], 1);
                float e1 = __shfl_xor_sync(0xffffffffu, dd[1], 1);
                float e2 = __shfl_xor_sync(0xffffffffu, dd[2], 1);
                float e3 = __shfl_xor_sync(0xffffffffu, dd[3], 1);
                const int b = (mtlo + q) * 16 + qr + (odd ? 8 : 0);

                float zi = odd ? e2 : dd[0];
                float zf = odd ? e3 : dd[1];
                float zo = odd ? dd[2] : e0;
                float zg = odd ? dd[3] : e1;

                zi += xv[q].x; zf += xv[q].y; zo += xv[q].z; zg += xv[q].w;

                const float ig = 1.0f / (1.0f + __expf(-zi));
                const float fg = 1.0f / (1.0f + __expf(-zf));
                const float og = 1.0f / (1.0f + __expf(-zo));
                const float gt = tanhf(zg);

                const float cn = fg * cv[q] + ig * gt;
                const float hn = og * tanhf(cn);
                cv[q] = cn;
                sh[b][lu] = hn;
            }
        }
        __syncthreads();

        // ---- write h_hi (fp16) for next step, parity pw ----
        if (tid < 64) {
            const int b = tid;
            char* dst = g_A + (size_t)(pw * 2 + dir) * A_PD +
                        (size_t)(nblk >> 2) * 8192 + (size_t)b * 128 + (nblk & 3) * 32;
            __half tmp[16];
#pragma unroll
            for (int q = 0; q < 16; q++) tmp[q] = __float2half_rn(sh[b][q]);
            *(uint4*)(dst)      = *(uint4*)(tmp);
            *(uint4*)(dst + 16) = *(uint4*)(tmp + 8);
        }

        // ---- coalesced out store: 64B runs per (b, t) ----
        {
            const int b = tid >> 3;
            const int e = tid & 7;
            float2 v;
            v.x = sh[b][e * 2];
            v.y = sh[b][e * 2 + 1];
            *(float2*)(out + (((size_t)b * TT + t) * 2 + dir) * HH +
                       nblk * 16 + e * 2) = v;
        }

        // ---- grid barrier + next-step xz prefetch during spin ----
        if (s < TT - 1) {
            __syncthreads();
            if (tid == 0) {
                asm volatile("red.release.gpu.global.add.u32 [%0], 1;"
                             :: "l"(&g_barrier) : "memory");
            }
            {
                const int tn = dir ? (TT - 2 - s) : (s + 1);
                const float* xz = g_xz + ((size_t)dir * TT + tn) * BB * GG;
#pragma unroll
                for (int q = 0; q < 2; q++) {
                    const int b = (mtlo + q) * 16 + qr + (odd ? 8 : 0);
                    xv[q] = *(const float4*)(xz + (size_t)b * GG + j * 4);
                }
            }
            if (tid == 0) {
                const unsigned target = 128u * (unsigned)(s + 1);
                unsigned v;
                do {
                    asm volatile("ld.acquire.gpu.global.u32 %0, [%1];"
                                 : "=r"(v) : "l"(&g_barrier) : "memory");
                } while (v < target);
            }
            __syncthreads();
        }
    }
}

// ---------------------------------------------------------------------------
extern "C" void kernel_launch(void* const* d_in, const int* in_sizes, int n_in,
                              void* d_out, int out_size) {
    const float* X    = (const float*)d_in[0];
    const float* Wx_f = (const float*)d_in[1];
    const float* Wh_f = (const float*)d_in[2];
    const float* b_f  = (const float*)d_in[3];
    const float* Wx_b = (const float*)d_in[4];
    const float* Wh_b = (const float*)d_in[5];
    const float* b_b  = (const float*)d_in[6];
    float* out = (float*)d_out;

    cudaFuncSetAttribute(lstm_kernel,
                         cudaFuncAttributeMaxDynamicSharedMemorySize, SM_TOTAL);

    init_kernel<<<512, 256>>>();
    convX_kernel<<<16384, 256>>>(X);
    convW_kernel<<<8192, 256>>>(Wh_f, Wh_b);
    convWx_kernel<<<4096, 256>>>(Wx_f, Wx_b, b_f, b_b);

    proj_kernel<<<dim3(32, 256, 2), 256>>>();

    lstm_kernel<<<dim3(64, 2), 512, SM_TOTAL>>>(out);
}

// round 10
// speedup vs baseline: 2.3074x; 1.1028x over previous
#include <cuda_runtime.h>
#include <cuda_fp16.h>
#include <math.h>
#include <stdint.h>

#define BB 64      // batch
#define TT 512     // seq len
#define DD 512     // input size
#define HH 1024    // hidden size
#define GG 4096    // 4*H

// ---------------------------------------------------------------------------
// Global scratch
// ---------------------------------------------------------------------------
__device__ float g_xz[(size_t)2 * TT * BB * GG];
// Wh fp16 (hi only), B-fragment order: [dir][nt(512)][kc16(64)][lane(32)]
__device__ uint2 g_Wfrag[(size_t)2 * 512 * 64 * 32];
// Wx fp16 (hi only), B-fragment order: [dir][nt(512)][kc16(32)][lane(32)]
__device__ uint2 g_Wxfrag[(size_t)2 * 512 * 32 * 32];
__device__ float g_biasp[2 * GG];
// X fp16 (hi only): [m(32768)][k(512)]
__device__ __half g_Xh[(size_t)32768 * 512];
// h fp16 (hi only): [parity][dir][kc64(16)][b(64)][64 halfs = 128B]
__device__ __align__(16) char g_A[(size_t)2 * 2 * 16 * 64 * 128];
__device__ unsigned g_barrier;

#define A_PD ((size_t)16 * 64 * 128)   // 131072 B per (parity,dir)

// smem layout (lstm kernel): 16 chunks x (64 rows x 144B) + sred + sh
#define SM_SRED  147456
#define SM_SH    (SM_SRED + 16384)        // 163840
#define SM_TOTAL (SM_SH + 64 * 17 * 4)    // 168192

// ---------------------------------------------------------------------------
#define MMA16816(d, a0, a1, a2, a3, b0, b1)                                  \
    asm volatile(                                                            \
        "mma.sync.aligned.m16n8k16.row.col.f32.f16.f16.f32 "                 \
        "{%0,%1,%2,%3}, {%4,%5,%6,%7}, {%8,%9}, {%0,%1,%2,%3};"              \
        : "+f"((d)[0]), "+f"((d)[1]), "+f"((d)[2]), "+f"((d)[3])             \
        : "r"(a0), "r"(a1), "r"(a2), "r"(a3), "r"(b0), "r"(b1))

#define LDSM_X4(r0, r1, r2, r3, addr)                                        \
    asm volatile(                                                            \
        "ldmatrix.sync.aligned.m8n8.x4.shared.b16 {%0,%1,%2,%3}, [%4];"      \
        : "=r"(r0), "=r"(r1), "=r"(r2), "=r"(r3) : "r"(addr))

#define CP16(dst, src)                                                       \
    asm volatile("cp.async.cg.shared.global [%0], [%1], 16;"                 \
                 :: "r"(dst), "l"(src))

__device__ __forceinline__ uint32_t smem_u32(const void* p) {
    uint32_t a;
    asm("{ .reg .u64 t; cvta.to.shared.u64 t, %1; cvt.u32.u64 %0, t; }"
        : "=r"(a) : "l"(p));
    return a;
}

// ---------------------------------------------------------------------------
__global__ void init_kernel() {
    int i = blockIdx.x * blockDim.x + threadIdx.x;   // 0..131071
    ((uint32_t*)g_A)[i] = 0u;                        // all 512KB of g_A
    if (i == 0) g_barrier = 0u;
}

// ---------------------------------------------------------------------------
__global__ void convX_kernel(const float* __restrict__ X) {
    size_t idx = (size_t)blockIdx.x * blockDim.x + threadIdx.x;
    float4 v = ((const float4*)X)[idx];
    __half h0 = __float2half_rn(v.x), h1 = __float2half_rn(v.y);
    __half h2 = __float2half_rn(v.z), h3 = __float2half_rn(v.w);
    uint2 hi;
    hi.x = (uint32_t)__half_as_ushort(h0) | ((uint32_t)__half_as_ushort(h1) << 16);
    hi.y = (uint32_t)__half_as_ushort(h2) | ((uint32_t)__half_as_ushort(h3) << 16);
    ((uint2*)g_Xh)[idx] = hi;
}

// ---------------------------------------------------------------------------
__global__ void convW_kernel(const float* __restrict__ Whf,
                             const float* __restrict__ Whb) {
    int idx = blockIdx.x * blockDim.x + threadIdx.x;   // 0 .. 2^21-1
    int lane = idx & 31;
    int kc   = (idx >> 5) & 63;
    int nt   = (idx >> 11) & 511;
    int dir  = idx >> 20;
    const float* W = dir ? Whb : Whf;

    int p   = nt * 8 + (lane >> 2);
    int col = ((p & 3) << 10) + (p >> 2);
    int k0  = kc * 16 + (lane & 3) * 2;

    float w0 = W[(size_t)(k0)     * GG + col];
    float w1 = W[(size_t)(k0 + 1) * GG + col];
    float w2 = W[(size_t)(k0 + 8) * GG + col];
    float w3 = W[(size_t)(k0 + 9) * GG + col];

    uint2 hi;
    hi.x = (uint32_t)__half_as_ushort(__float2half_rn(w0)) |
           ((uint32_t)__half_as_ushort(__float2half_rn(w1)) << 16);
    hi.y = (uint32_t)__half_as_ushort(__float2half_rn(w2)) |
           ((uint32_t)__half_as_ushort(__float2half_rn(w3)) << 16);

    g_Wfrag[(((size_t)dir * 512 + nt) * 64 + kc) * 32 + lane] = hi;
}

// ---------------------------------------------------------------------------
__global__ void convWx_kernel(const float* __restrict__ Wxf,
                              const float* __restrict__ Wxb,
                              const float* __restrict__ bf,
                              const float* __restrict__ bb) {
    int idx = blockIdx.x * blockDim.x + threadIdx.x;   // 0 .. 2^20-1
    int lane = idx & 31;
    int kc   = (idx >> 5) & 31;
    int nt   = (idx >> 10) & 511;
    int dir  = idx >> 19;
    const float* W = dir ? Wxb : Wxf;

    int p   = nt * 8 + (lane >> 2);
    int col = ((p & 3) << 10) + (p >> 2);
    int k0  = kc * 16 + (lane & 3) * 2;

    float w0 = W[(size_t)(k0)     * GG + col];
    float w1 = W[(size_t)(k0 + 1) * GG + col];
    float w2 = W[(size_t)(k0 + 8) * GG + col];
    float w3 = W[(size_t)(k0 + 9) * GG + col];

    uint2 hi;
    hi.x = (uint32_t)__half_as_ushort(__float2half_rn(w0)) |
           ((uint32_t)__half_as_ushort(__float2half_rn(w1)) << 16);
    hi.y = (uint32_t)__half_as_ushort(__float2half_rn(w2)) |
           ((uint32_t)__half_as_ushort(__float2half_rn(w3)) << 16);

    g_Wxfrag[(((size_t)dir * 512 + nt) * 32 + kc) * 32 + lane] = hi;

    if (kc == 0 && (lane & 3) == 0) {
        const float* bias = dir ? bb : bf;
        g_biasp[dir * GG + p] = bias[col];
    }
}

// ---------------------------------------------------------------------------
// Input projection: 1-term fp16 mma (X_hi @ W_hi).
// ---------------------------------------------------------------------------
__global__ void __launch_bounds__(256, 1) proj_kernel() {
    __shared__ __align__(16) char sX[2 * 6144];   // 2 buf x 128 rows x 48B

    const int dir = blockIdx.z;
    const int n0 = blockIdx.x * 128;
    const int m0 = blockIdx.y * 128;
    const int tid = threadIdx.x;
    const int warp = tid >> 5, lane = tid & 31;
    const int wm = warp >> 2, wn = warp & 3;
    const int qr = lane >> 2, qc = lane & 3;

    const uint2* WX = g_Wxfrag + (size_t)dir * 512 * 32 * 32;
    const int ntbase = (n0 >> 3) + wn * 4;

    const uint32_t sX0 = smem_u32(sX);

    auto stage = [&](int c) {
        const int row = tid >> 1, q = tid & 1;
        const char* src = (const char*)g_Xh +
                          (((size_t)(m0 + row) * 512 + c * 16) << 1) + q * 16;
        const uint32_t dst = sX0 + (c & 1) * 6144 + row * 48 + q * 16;
        CP16(dst, src);
    };

    float d[4][4][4] = {};

    stage(0);
    asm volatile("cp.async.commit_group;" ::: "memory");

    for (int c = 0; c < 32; c++) {
        __syncthreads();
        if (c < 31) {
            stage(c + 1);
            asm volatile("cp.async.commit_group;" ::: "memory");
            asm volatile("cp.async.wait_group 1;" ::: "memory");
        } else {
            asm volatile("cp.async.wait_group 0;" ::: "memory");
        }
        __syncthreads();

        uint2 bh[4];
#pragma unroll
        for (int nt = 0; nt < 4; nt++)
            bh[nt] = WX[(((size_t)(ntbase + nt)) * 32 + c) * 32 + lane];

        const uint32_t slot = sX0 + (c & 1) * 6144;
        const uint32_t lrow = (lane & 15) * 48 + ((lane >> 4) << 4);
#pragma unroll
        for (int mt = 0; mt < 4; mt++) {
            const uint32_t arow = slot + (wm * 64 + mt * 16) * 48 + lrow;
            uint32_t a0, a1, a2, a3;
            LDSM_X4(a0, a1, a2, a3, arow);
#pragma unroll
            for (int nt = 0; nt < 4; nt++)
                MMA16816(d[mt][nt], a0, a1, a2, a3, bh[nt].x, bh[nt].y);
        }
    }

#pragma unroll
    for (int mt = 0; mt < 4; mt++) {
#pragma unroll
        for (int nt = 0; nt < 4; nt++) {
            const int n = n0 + wn * 32 + nt * 8 + qc * 2;
            const float2 bv = *(const float2*)(g_biasp + dir * GG + n);
            const int ma = m0 + wm * 64 + mt * 16 + qr;
            const int mb = ma + 8;
            float2 v0, v1;
            v0.x = d[mt][nt][0] + bv.x; v0.y = d[mt][nt][1] + bv.y;
            v1.x = d[mt][nt][2] + bv.x; v1.y = d[mt][nt][3] + bv.y;
            *(float2*)(g_xz + (((size_t)dir * TT + (ma & 511)) * BB + (ma >> 9)) * GG + n) = v0;
            *(float2*)(g_xz + (((size_t)dir * TT + (mb & 511)) * BB + (mb >> 9)) * GG + n) = v1;
        }
    }
}

// ---------------------------------------------------------------------------
// Persistent recurrence: grid (64,2), 512 threads (8 ntiles x 2 kh).
// 1-term fp16 mma; full A_hi staged into smem once per step (2 convoys).
// ---------------------------------------------------------------------------
__global__ void __launch_bounds__(512, 1) lstm_kernel(float* __restrict__ out) {
    extern __shared__ char dsm[];
    const uint32_t sA0 = smem_u32(dsm);               // 16 chunks x 64 x 144B
    float* sred = (float*)(dsm + SM_SRED);            // [2kh][8ntw][8][32]
    float (*sh)[17] = (float(*)[17])(dsm + SM_SH);    // [64][17]

    const int dir  = blockIdx.y;
    const int nblk = blockIdx.x;                      // 0..63
    const int tid  = threadIdx.x;
    const int warp = tid >> 5;
    const int lane = tid & 31;
    const int ntw = warp & 7;
    const int kh  = warp >> 3;
    const int qr = lane >> 2;
    const int qc = lane & 3;
    const int ntg = nblk * 8 + ntw;

    const uint2* Bh = g_Wfrag + (((size_t)dir * 512 + ntg) * 64) * 32 + lane;

    const int u = qc >> 1;
    const int j = nblk * 16 + ntw * 2 + u;
    const bool odd = qc & 1;
    const int lu = ntw * 2 + u;
    const int mtlo = kh * 2;                          // this warp's epilogue mt pair

    const int st_b = tid >> 3;
    const int st_q = tid & 7;

    float cv[2] = {0.0f, 0.0f};

    float4 xv[2];
    {
        const int t0 = dir ? (TT - 1) : 0;
        const float* xz = g_xz + ((size_t)dir * TT + t0) * BB * GG;
#pragma unroll
        for (int q = 0; q < 2; q++) {
            const int b = (mtlo + q) * 16 + qr + (odd ? 8 : 0);
            xv[q] = *(const float4*)(xz + (size_t)b * GG + j * 4);
        }
    }

    for (int s = 0; s < TT; s++) {
        const int t  = dir ? (TT - 1 - s) : s;
        const int pr = s & 1;
        const int pw = pr ^ 1;
        const char* srcA = g_A + (size_t)(pr * 2 + dir) * A_PD;

        // ---- stage all 16 chunks in 2 groups ----
        // group0 -> chunks {0..3, 8..11}, group1 -> chunks {4..7, 12..15}
#pragma unroll
        for (int g = 0; g < 2; g++) {
#pragma unroll
            for (int r = 0; r < 8; r++) {
                const int ci = g * 8 + r;
                const int chunk = (ci & 3) + (((ci >> 2) & 1) << 3) + ((ci >> 3) << 2);
                const char* src = srcA + (size_t)chunk * 8192 + st_b * 128 + st_q * 16;
                const uint32_t dst = sA0 + chunk * 9216 + st_b * 144 + st_q * 16;
                CP16(dst, src);
            }
            asm volatile("cp.async.commit_group;" ::: "memory");
        }

        float d[4][4] = {};

        // ---- compute: 2 phases x 4 chunks x 4 ksteps ----
#pragma unroll
        for (int phase = 0; phase < 2; phase++) {
            // W fragments for this phase's first chunk (prefetch before wait)
            const int chunk0 = kh * 8 + phase * 4;
            uint2 wh[4];
#pragma unroll
            for (int sub = 0; sub < 4; sub++)
                wh[sub] = Bh[(size_t)(chunk0 * 4 + sub) * 32];

            if (phase == 0) {
                asm volatile("cp.async.wait_group 1;" ::: "memory");
            } else {
                asm volatile("cp.async.wait_group 0;" ::: "memory");
            }
            __syncthreads();

#pragma unroll
            for (int cc = 0; cc < 4; cc++) {
                const int chunk = chunk0 + cc;
                uint2 whn[4];
                if (cc < 3) {   // prefetch next chunk's W fragments
#pragma unroll
                    for (int sub = 0; sub < 4; sub++)
                        whn[sub] = Bh[(size_t)((chunk + 1) * 4 + sub) * 32];
                }
                const uint32_t slot = sA0 + chunk * 9216;
                const uint32_t lrow = (lane & 15) * 144 + ((lane >> 4) << 4);
#pragma unroll
                for (int sub = 0; sub < 4; sub++) {
                    const uint32_t arow = slot + sub * 32 + lrow;
#pragma unroll
                    for (int mt = 0; mt < 4; mt++) {
                        uint32_t a0, a1, a2, a3;
                        LDSM_X4(a0, a1, a2, a3, arow + mt * 2304);
                        MMA16816(d[mt], a0, a1, a2, a3, wh[sub].x, wh[sub].y);
                    }
                }
                if (cc < 3) {
#pragma unroll
                    for (int sub = 0; sub < 4; sub++) wh[sub] = whn[sub];
                }
            }
        }

        // ---- partial exchange: each kh group exports the other's mt pair ----
        {
            const int omt = 2 - mtlo;
#pragma unroll
            for (int q = 0; q < 2; q++)
#pragma unroll
                for (int e = 0; e < 4; e++)
                    sred[(((kh * 8 + ntw) * 8) + q * 4 + e) * 32 + lane] = d[omt + q][e];
        }
        __syncthreads();

        // ---- reduce + gate math for this warp's mt pair ----
        {
            const int okh = kh ^ 1;
#pragma unroll
            for (int q = 0; q < 2; q++) {
#pragma unroll
                for (int e = 0; e < 4; e++)
                    d[mtlo + q][e] += sred[(((okh * 8 + ntw) * 8) + q * 4 + e) * 32 + lane];

                float* dd = d[mtlo + q];
                float e0 = __shfl_xor_sync(0xffffffffu, dd[0], 1);
                float e1 = __shfl_xor_sync(0xffffffffu, dd[1], 1);
                float e2 = __shfl_xor_sync(0xffffffffu, dd[2], 1);
                float e3 = __shfl_xor_sync(0xffffffffu, dd[3], 1);
                const int b = (mtlo + q) * 16 + qr + (odd ? 8 : 0);

                float zi = odd ? e2 : dd[0];
                float zf = odd ? e3 : dd[1];
                float zo = odd ? dd[2] : e0;
                float zg = odd ? dd[3] : e1;

                zi += xv[q].x; zf += xv[q].y; zo += xv[q].z; zg += xv[q].w;

                const float ig = 1.0f / (1.0f + __expf(-zi));
                const float fg = 1.0f / (1.0f + __expf(-zf));
                const float og = 1.0f / (1.0f + __expf(-zo));
                const float gt = tanhf(zg);

                const float cn = fg * cv[q] + ig * gt;
                const float hn = og * tanhf(cn);
                cv[q] = cn;
                sh[b][lu] = hn;
            }
        }
        __syncthreads();

        // ---- write h_hi (fp16) for next step, parity pw ----
        if (tid < 64) {
            const int b = tid;
            char* dst = g_A + (size_t)(pw * 2 + dir) * A_PD +
                        (size_t)(nblk >> 2) * 8192 + (size_t)b * 128 + (nblk & 3) * 32;
            __half tmp[16];
#pragma unroll
            for (int q = 0; q < 16; q++) tmp[q] = __float2half_rn(sh[b][q]);
            *(uint4*)(dst)      = *(uint4*)(tmp);
            *(uint4*)(dst + 16) = *(uint4*)(tmp + 8);
        }

        // ---- coalesced out store: 64B runs per (b, t) ----
        {
            const int b = tid >> 3;
            const int e = tid & 7;
            float2 v;
            v.x = sh[b][e * 2];
            v.y = sh[b][e * 2 + 1];
            *(float2*)(out + (((size_t)b * TT + t) * 2 + dir) * HH +
                       nblk * 16 + e * 2) = v;
        }

        // ---- grid barrier + next-step xz prefetch during spin ----
        if (s < TT - 1) {
            __syncthreads();
            if (tid == 0) {
                asm volatile("red.release.gpu.global.add.u32 [%0], 1;"
                             :: "l"(&g_barrier) : "memory");
            }
            {
                const int tn = dir ? (TT - 2 - s) : (s + 1);
                const float* xz = g_xz + ((size_t)dir * TT + tn) * BB * GG;
#pragma unroll
                for (int q = 0; q < 2; q++) {
                    const int b = (mtlo + q) * 16 + qr + (odd ? 8 : 0);
                    xv[q] = *(const float4*)(xz + (size_t)b * GG + j * 4);
                }
            }
            if (tid == 0) {
                const unsigned target = 128u * (unsigned)(s + 1);
                unsigned v;
                do {
                    asm volatile("ld.acquire.gpu.global.u32 %0, [%1];"
                                 : "=r"(v) : "l"(&g_barrier) : "memory");
                } while (v < target);
            }
            __syncthreads();
        }
    }
}

// ---------------------------------------------------------------------------
extern "C" void kernel_launch(void* const* d_in, const int* in_sizes, int n_in,
                              void* d_out, int out_size) {
    const float* X    = (const float*)d_in[0];
    const float* Wx_f = (const float*)d_in[1];
    const float* Wh_f = (const float*)d_in[2];
    const float* b_f  = (const float*)d_in[3];
    const float* Wx_b = (const float*)d_in[4];
    const float* Wh_b = (const float*)d_in[5];
    const float* b_b  = (const float*)d_in[6];
    float* out = (float*)d_out;

    cudaFuncSetAttribute(lstm_kernel,
                         cudaFuncAttributeMaxDynamicSharedMemorySize, SM_TOTAL);

    init_kernel<<<512, 256>>>();
    convX_kernel<<<16384, 256>>>(X);
    convW_kernel<<<8192, 256>>>(Wh_f, Wh_b);
    convWx_kernel<<<4096, 256>>>(Wx_f, Wx_b, b_f, b_b);

    proj_kernel<<<dim3(32, 256, 2), 256>>>();

    lstm_kernel<<<dim3(64, 2), 512, SM_TOTAL>>>(out);
}

// round 11
// speedup vs baseline: 2.4651x; 1.0683x over previous
#include <cuda_runtime.h>
#include <cuda_fp16.h>
#include <math.h>
#include <stdint.h>

#define BB 64      // batch
#define TT 512     // seq len
#define DD 512     // input size
#define HH 1024    // hidden size
#define GG 4096    // 4*H

// ---------------------------------------------------------------------------
// Global scratch
// ---------------------------------------------------------------------------
__device__ float g_xz[(size_t)2 * TT * BB * GG];
// Wh fp16 (hi only), B-fragment order: [dir][nt(512)][kc16(64)][lane(32)]
__device__ uint2 g_Wfrag[(size_t)2 * 512 * 64 * 32];
// Wx fp16 (hi only), B-fragment order: [dir][nt(512)][kc16(32)][lane(32)]
__device__ uint2 g_Wxfrag[(size_t)2 * 512 * 32 * 32];
__device__ float g_biasp[2 * GG];
// X fp16 (hi only): [m(32768)][k(512)]
__device__ __half g_Xh[(size_t)32768 * 512];
// h fp16 (hi only): [parity][dir][kc64(16)][b(64)][64 halfs = 128B]
__device__ __align__(16) char g_A[(size_t)2 * 2 * 16 * 64 * 128];
__device__ unsigned g_barrier;

#define A_PD ((size_t)16 * 64 * 128)   // 131072 B per (parity,dir)

// smem: 16 chunks x (64 rows x 144B) = 147456; sred (64KB) + sh overlay it
#define SM_SH    90112
#define SM_TOTAL 147456

// ---------------------------------------------------------------------------
#define MMA16816(d, a0, a1, a2, a3, b0, b1)                                  \
    asm volatile(                                                            \
        "mma.sync.aligned.m16n8k16.row.col.f32.f16.f16.f32 "                 \
        "{%0,%1,%2,%3}, {%4,%5,%6,%7}, {%8,%9}, {%0,%1,%2,%3};"              \
        : "+f"((d)[0]), "+f"((d)[1]), "+f"((d)[2]), "+f"((d)[3])             \
        : "r"(a0), "r"(a1), "r"(a2), "r"(a3), "r"(b0), "r"(b1))

#define LDSM_X4(r0, r1, r2, r3, addr)                                        \
    asm volatile(                                                            \
        "ldmatrix.sync.aligned.m8n8.x4.shared.b16 {%0,%1,%2,%3}, [%4];"      \
        : "=r"(r0), "=r"(r1), "=r"(r2), "=r"(r3) : "r"(addr))

#define CP16(dst, src)                                                       \
    asm volatile("cp.async.cg.shared.global [%0], [%1], 16;"                 \
                 :: "r"(dst), "l"(src))

__device__ __forceinline__ uint32_t smem_u32(const void* p) {
    uint32_t a;
    asm("{ .reg .u64 t; cvta.to.shared.u64 t, %1; cvt.u32.u64 %0, t; }"
        : "=r"(a) : "l"(p));
    return a;
}

// ---------------------------------------------------------------------------
__global__ void init_kernel() {
    int i = blockIdx.x * blockDim.x + threadIdx.x;   // 0..131071
    ((uint32_t*)g_A)[i] = 0u;
    if (i == 0) g_barrier = 0u;
}

// ---------------------------------------------------------------------------
__global__ void convX_kernel(const float* __restrict__ X) {
    size_t idx = (size_t)blockIdx.x * blockDim.x + threadIdx.x;
    float4 v = ((const float4*)X)[idx];
    __half h0 = __float2half_rn(v.x), h1 = __float2half_rn(v.y);
    __half h2 = __float2half_rn(v.z), h3 = __float2half_rn(v.w);
    uint2 hi;
    hi.x = (uint32_t)__half_as_ushort(h0) | ((uint32_t)__half_as_ushort(h1) << 16);
    hi.y = (uint32_t)__half_as_ushort(h2) | ((uint32_t)__half_as_ushort(h3) << 16);
    ((uint2*)g_Xh)[idx] = hi;
}

// ---------------------------------------------------------------------------
__global__ void convW_kernel(const float* __restrict__ Whf,
                             const float* __restrict__ Whb) {
    int idx = blockIdx.x * blockDim.x + threadIdx.x;
    int lane = idx & 31;
    int kc   = (idx >> 5) & 63;
    int nt   = (idx >> 11) & 511;
    int dir  = idx >> 20;
    const float* W = dir ? Whb : Whf;

    int p   = nt * 8 + (lane >> 2);
    int col = ((p & 3) << 10) + (p >> 2);
    int k0  = kc * 16 + (lane & 3) * 2;

    float w0 = W[(size_t)(k0)     * GG + col];
    float w1 = W[(size_t)(k0 + 1) * GG + col];
    float w2 = W[(size_t)(k0 + 8) * GG + col];
    float w3 = W[(size_t)(k0 + 9) * GG + col];

    uint2 hi;
    hi.x = (uint32_t)__half_as_ushort(__float2half_rn(w0)) |
           ((uint32_t)__half_as_ushort(__float2half_rn(w1)) << 16);
    hi.y = (uint32_t)__half_as_ushort(__float2half_rn(w2)) |
           ((uint32_t)__half_as_ushort(__float2half_rn(w3)) << 16);

    g_Wfrag[(((size_t)dir * 512 + nt) * 64 + kc) * 32 + lane] = hi;
}

// ---------------------------------------------------------------------------
__global__ void convWx_kernel(const float* __restrict__ Wxf,
                              const float* __restrict__ Wxb,
                              const float* __restrict__ bf,
                              const float* __restrict__ bb) {
    int idx = blockIdx.x * blockDim.x + threadIdx.x;
    int lane = idx & 31;
    int kc   = (idx >> 5) & 31;
    int nt   = (idx >> 10) & 511;
    int dir  = idx >> 19;
    const float* W = dir ? Wxb : Wxf;

    int p   = nt * 8 + (lane >> 2);
    int col = ((p & 3) << 10) + (p >> 2);
    int k0  = kc * 16 + (lane & 3) * 2;

    float w0 = W[(size_t)(k0)     * GG + col];
    float w1 = W[(size_t)(k0 + 1) * GG + col];
    float w2 = W[(size_t)(k0 + 8) * GG + col];
    float w3 = W[(size_t)(k0 + 9) * GG + col];

    uint2 hi;
    hi.x = (uint32_t)__half_as_ushort(__float2half_rn(w0)) |
           ((uint32_t)__half_as_ushort(__float2half_rn(w1)) << 16);
    hi.y = (uint32_t)__half_as_ushort(__float2half_rn(w2)) |
           ((uint32_t)__half_as_ushort(__float2half_rn(w3)) << 16);

    g_Wxfrag[(((size_t)dir * 512 + nt) * 32 + kc) * 32 + lane] = hi;

    if (kc == 0 && (lane & 3) == 0) {
        const float* bias = dir ? bb : bf;
        g_biasp[dir * GG + p] = bias[col];
    }
}

// ---------------------------------------------------------------------------
// Input projection: 1-term fp16 mma (X_hi @ W_hi).  (unchanged from R10)
// ---------------------------------------------------------------------------
__global__ void __launch_bounds__(256, 1) proj_kernel() {
    __shared__ __align__(16) char sX[2 * 6144];

    const int dir = blockIdx.z;
    const int n0 = blockIdx.x * 128;
    const int m0 = blockIdx.y * 128;
    const int tid = threadIdx.x;
    const int warp = tid >> 5, lane = tid & 31;
    const int wm = warp >> 2, wn = warp & 3;
    const int qr = lane >> 2, qc = lane & 3;

    const uint2* WX = g_Wxfrag + (size_t)dir * 512 * 32 * 32;
    const int ntbase = (n0 >> 3) + wn * 4;

    const uint32_t sX0 = smem_u32(sX);

    auto stage = [&](int c) {
        const int row = tid >> 1, q = tid & 1;
        const char* src = (const char*)g_Xh +
                          (((size_t)(m0 + row) * 512 + c * 16) << 1) + q * 16;
        const uint32_t dst = sX0 + (c & 1) * 6144 + row * 48 + q * 16;
        CP16(dst, src);
    };

    float d[4][4][4] = {};

    stage(0);
    asm volatile("cp.async.commit_group;" ::: "memory");

    for (int c = 0; c < 32; c++) {
        __syncthreads();
        if (c < 31) {
            stage(c + 1);
            asm volatile("cp.async.commit_group;" ::: "memory");
            asm volatile("cp.async.wait_group 1;" ::: "memory");
        } else {
            asm volatile("cp.async.wait_group 0;" ::: "memory");
        }
        __syncthreads();

        uint2 bh[4];
#pragma unroll
        for (int nt = 0; nt < 4; nt++)
            bh[nt] = WX[(((size_t)(ntbase + nt)) * 32 + c) * 32 + lane];

        const uint32_t slot = sX0 + (c & 1) * 6144;
        const uint32_t lrow = (lane & 15) * 48 + ((lane >> 4) << 4);
#pragma unroll
        for (int mt = 0; mt < 4; mt++) {
            const uint32_t arow = slot + (wm * 64 + mt * 16) * 48 + lrow;
            uint32_t a0, a1, a2, a3;
            LDSM_X4(a0, a1, a2, a3, arow);
#pragma unroll
            for (int nt = 0; nt < 4; nt++)
                MMA16816(d[mt][nt], a0, a1, a2, a3, bh[nt].x, bh[nt].y);
        }
    }

#pragma unroll
    for (int mt = 0; mt < 4; mt++) {
#pragma unroll
        for (int nt = 0; nt < 4; nt++) {
            const int n = n0 + wn * 32 + nt * 8 + qc * 2;
            const float2 bv = *(const float2*)(g_biasp + dir * GG + n);
            const int ma = m0 + wm * 64 + mt * 16 + qr;
            const int mb = ma + 8;
            float2 v0, v1;
            v0.x = d[mt][nt][0] + bv.x; v0.y = d[mt][nt][1] + bv.y;
            v1.x = d[mt][nt][2] + bv.x; v1.y = d[mt][nt][3] + bv.y;
            *(float2*)(g_xz + (((size_t)dir * TT + (ma & 511)) * BB + (ma >> 9)) * GG + n) = v0;
            *(float2*)(g_xz + (((size_t)dir * TT + (mb & 511)) * BB + (mb >> 9)) * GG + n) = v1;
        }
    }
}

// ---------------------------------------------------------------------------
// Persistent recurrence: grid (64,2), 512 threads = 4 ntw x 4 kh warps.
// Each warp: 2 ntiles x 4 k-chunks; A fragment reused for 2 MMAs -> smem
// crossbar reads halved. 4-way k reduction via sred overlaying A region.
// ---------------------------------------------------------------------------
__global__ void __launch_bounds__(512, 1) lstm_kernel(float* __restrict__ out) {
    extern __shared__ char dsm[];
    const uint32_t sA0 = smem_u32(dsm);               // 16 chunks x 64 x 144B
    float* sred = (float*)dsm;                        // overlays A (64KB)
    float (*sh)[17] = (float(*)[17])(dsm + SM_SH);    // [64][17] overlays A

    const int dir  = blockIdx.y;
    const int nblk = blockIdx.x;                      // 0..63
    const int tid  = threadIdx.x;
    const int warp = tid >> 5;
    const int lane = tid & 31;
    const int ntw = warp & 3;                         // 0..3: 2 ntiles each
    const int kh  = warp >> 2;                        // 0..3: 4 chunks each
    const int qr = lane >> 2;
    const int qc = lane & 3;
    const int ntg0 = nblk * 8 + ntw * 2;

    // B fragments for this warp's 2 ntiles (nt stride = 64*32 uint2)
    const uint2* Bh = g_Wfrag + (((size_t)dir * 512 + ntg0) * 64) * 32 + lane;

    const int u = qc >> 1;
    const bool odd = qc & 1;
    const int mt = kh;                                // epilogue row tile
    const int bq = mt * 16 + qr + (odd ? 8 : 0);      // epilogue batch row

    const int st_b = tid >> 3;
    const int st_q = tid & 7;

    float cv[2] = {0.0f, 0.0f};

    float4 xv[2];
    {
        const int t0 = dir ? (TT - 1) : 0;
        const float* xz = g_xz + ((size_t)dir * TT + t0) * BB * GG;
#pragma unroll
        for (int q = 0; q < 2; q++) {
            const int jq = nblk * 16 + (ntw * 2 + q) * 2 + u;
            xv[q] = *(const float4*)(xz + (size_t)bq * GG + jq * 4);
        }
    }

    for (int s = 0; s < TT; s++) {
        const int t  = dir ? (TT - 1 - s) : s;
        const int pr = s & 1;
        const int pw = pr ^ 1;
        const char* srcA = g_A + (size_t)(pr * 2 + dir) * A_PD;

        // ---- stage all 16 chunks in 2 groups ----
        // phase p (for warp kh) uses chunks kh*4 + p*2 + {0,1}; bit1 == p,
        // so group g = chunks with bit1 == g.
#pragma unroll
        for (int g = 0; g < 2; g++) {
#pragma unroll
            for (int ci = 0; ci < 8; ci++) {
                const int chunk = ((ci >> 1) << 2) | (g << 1) | (ci & 1);
                const char* src = srcA + (size_t)chunk * 8192 + st_b * 128 + st_q * 16;
                const uint32_t dst = sA0 + chunk * 9216 + st_b * 144 + st_q * 16;
                CP16(dst, src);
            }
            asm volatile("cp.async.commit_group;" ::: "memory");
        }

        float d[4][2][4] = {};

        // ---- compute: 2 phases x 2 chunks x 4 ksteps, 2 nt per A frag ----
#pragma unroll
        for (int phase = 0; phase < 2; phase++) {
            const int chunk0 = kh * 4 + phase * 2;
            // prefetch W frags for this phase's first chunk before the wait
            uint2 wh[4][2];
#pragma unroll
            for (int sub = 0; sub < 4; sub++)
#pragma unroll
                for (int nq = 0; nq < 2; nq++)
                    wh[sub][nq] = Bh[((size_t)nq * 64 + chunk0 * 4 + sub) * 32];

            if (phase == 0) {
                asm volatile("cp.async.wait_group 1;" ::: "memory");
            } else {
                asm volatile("cp.async.wait_group 0;" ::: "memory");
            }
            __syncthreads();

#pragma unroll
            for (int cc = 0; cc < 2; cc++) {
                const int chunk = chunk0 + cc;
                uint2 whn[4][2];
                if (cc < 1) {   // prefetch next chunk's W fragments
#pragma unroll
                    for (int sub = 0; sub < 4; sub++)
#pragma unroll
                        for (int nq = 0; nq < 2; nq++)
                            whn[sub][nq] =
                                Bh[((size_t)nq * 64 + (chunk + 1) * 4 + sub) * 32];
                }
                const uint32_t slot = sA0 + chunk * 9216;
                const uint32_t lrow = (lane & 15) * 144 + ((lane >> 4) << 4);
#pragma unroll
                for (int sub = 0; sub < 4; sub++) {
                    const uint32_t arow = slot + sub * 32 + lrow;
#pragma unroll
                    for (int m = 0; m < 4; m++) {
                        uint32_t a0, a1, a2, a3;
                        LDSM_X4(a0, a1, a2, a3, arow + m * 2304);
                        MMA16816(d[m][0], a0, a1, a2, a3, wh[sub][0].x, wh[sub][0].y);
                        MMA16816(d[m][1], a0, a1, a2, a3, wh[sub][1].x, wh[sub][1].y);
                    }
                }
                if (cc < 1) {
#pragma unroll
                    for (int sub = 0; sub < 4; sub++) {
                        wh[sub][0] = whn[sub][0];
                        wh[sub][1] = whn[sub][1];
                    }
                }
            }
        }

        // ---- 4-way k reduction via sred (overlays A; guard the WAR) ----
        __syncthreads();   // all LDSM reads of A region complete
        {
            const int wbase = (kh * 4 + ntw) * 1024;
#pragma unroll
            for (int m = 0; m < 4; m++)
#pragma unroll
                for (int nq = 0; nq < 2; nq++)
#pragma unroll
                    for (int e = 0; e < 4; e++)
                        sred[wbase + (m * 8 + nq * 4 + e) * 32 + lane] = d[m][nq][e];
        }
        __syncthreads();

        // ---- reduce + gate math: warp (ntw,kh) owns mt=kh, its 2 ntiles ----
        {
#pragma unroll
            for (int q = 0; q < 2; q++) {
                float z0 = d[mt][q][0], z1 = d[mt][q][1];
                float z2 = d[mt][q][2], z3 = d[mt][q][3];
#pragma unroll
                for (int src = 0; src < 4; src++) {
                    if (src == kh) continue;
                    const int rb = (src * 4 + ntw) * 1024 + (mt * 8 + q * 4) * 32 + lane;
                    z0 += sred[rb];
                    z1 += sred[rb + 32];
                    z2 += sred[rb + 64];
                    z3 += sred[rb + 96];
                }
                float e0 = __shfl_xor_sync(0xffffffffu, z0, 1);
                float e1 = __shfl_xor_sync(0xffffffffu, z1, 1);
                float e2 = __shfl_xor_sync(0xffffffffu, z2, 1);
                float e3 = __shfl_xor_sync(0xffffffffu, z3, 1);

                float zi = odd ? e2 : z0;
                float zf = odd ? e3 : z1;
                float zo = odd ? z2 : e0;
                float zg = odd ? z3 : e1;

                zi += xv[q].x; zf += xv[q].y; zo += xv[q].z; zg += xv[q].w;

                const float ig = 1.0f / (1.0f + __expf(-zi));
                const float fg = 1.0f / (1.0f + __expf(-zf));
                const float og = 1.0f / (1.0f + __expf(-zo));
                const float gt = tanhf(zg);

                const float cn = fg * cv[q] + ig * gt;
                const float hn = og * tanhf(cn);
                cv[q] = cn;
                sh[bq][(ntw * 2 + q) * 2 + u] = hn;
            }
        }
        __syncthreads();

        // ---- write h_hi (fp16) for next step, parity pw ----
        if (tid < 64) {
            const int b = tid;
            char* dst = g_A + (size_t)(pw * 2 + dir) * A_PD +
                        (size_t)(nblk >> 2) * 8192 + (size_t)b * 128 + (nblk & 3) * 32;
            __half tmp[16];
#pragma unroll
            for (int q = 0; q < 16; q++) tmp[q] = __float2half_rn(sh[b][q]);
            *(uint4*)(dst)      = *(uint4*)(tmp);
            *(uint4*)(dst + 16) = *(uint4*)(tmp + 8);
        }

        // ---- coalesced out store: 64B runs per (b, t) ----
        {
            const int b = tid >> 3;
            const int e = tid & 7;
            float2 v;
            v.x = sh[b][e * 2];
            v.y = sh[b][e * 2 + 1];
            *(float2*)(out + (((size_t)b * TT + t) * 2 + dir) * HH +
                       nblk * 16 + e * 2) = v;
        }

        // ---- grid barrier + next-step xz prefetch during spin ----
        if (s < TT - 1) {
            __syncthreads();
            if (tid == 0) {
                asm volatile("red.release.gpu.global.add.u32 [%0], 1;"
                             :: "l"(&g_barrier) : "memory");
            }
            {
                const int tn = dir ? (TT - 2 - s) : (s + 1);
                const float* xz = g_xz + ((size_t)dir * TT + tn) * BB * GG;
#pragma unroll
                for (int q = 0; q < 2; q++) {
                    const int jq = nblk * 16 + (ntw * 2 + q) * 2 + u;
                    xv[q] = *(const float4*)(xz + (size_t)bq * GG + jq * 4);
                }
            }
            if (tid == 0) {
                const unsigned target = 128u * (unsigned)(s + 1);
                unsigned v;
                do {
                    asm volatile("ld.acquire.gpu.global.u32 %0, [%1];"
                                 : "=r"(v) : "l"(&g_barrier) : "memory");
                } while (v < target);
            }
            __syncthreads();
        }
    }
}

// ---------------------------------------------------------------------------
extern "C" void kernel_launch(void* const* d_in, const int* in_sizes, int n_in,
                              void* d_out, int out_size) {
    const float* X    = (const float*)d_in[0];
    const float* Wx_f = (const float*)d_in[1];
    const float* Wh_f = (const float*)d_in[2];
    const float* b_f  = (const float*)d_in[3];
    const float* Wx_b = (const float*)d_in[4];
    const float* Wh_b = (const float*)d_in[5];
    const float* b_b  = (const float*)d_in[6];
    float* out = (float*)d_out;

    cudaFuncSetAttribute(lstm_kernel,
                         cudaFuncAttributeMaxDynamicSharedMemorySize, SM_TOTAL);

    init_kernel<<<512, 256>>>();
    convX_kernel<<<16384, 256>>>(X);
    convW_kernel<<<8192, 256>>>(Wh_f, Wh_b);
    convWx_kernel<<<4096, 256>>>(Wx_f, Wx_b, b_f, b_b);

    proj_kernel<<<dim3(32, 256, 2), 256>>>();

    lstm_kernel<<<dim3(64, 2), 512, SM_TOTAL>>>(out);
}

// round 12
// speedup vs baseline: 2.8335x; 1.1494x over previous
#include <cuda_runtime.h>
#include <cuda_fp16.h>
#include <math.h>
#include <stdint.h>

#define BB 64      // batch
#define TT 512     // seq len
#define DD 512     // input size
#define HH 1024    // hidden size
#define GG 4096    // 4*H

// ---------------------------------------------------------------------------
// Global scratch
// ---------------------------------------------------------------------------
__device__ float g_xz[(size_t)2 * TT * BB * GG];
// Wh fp16 (hi only), B-fragment order: [dir][nt(512)][kc16(64)][lane(32)]
__device__ uint2 g_Wfrag[(size_t)2 * 512 * 64 * 32];
// Wx fp16 (hi only), B-fragment order: [dir][nt(512)][kc16(32)][lane(32)]
__device__ uint2 g_Wxfrag[(size_t)2 * 512 * 32 * 32];
__device__ float g_biasp[2 * GG];
// X fp16 (hi only): [m(32768)][k(512)]
__device__ __half g_Xh[(size_t)32768 * 512];
// h fp16 (hi only): [parity][dir][kc64(16)][b(64)][64 halfs = 128B]
__device__ __align__(16) char g_A[(size_t)2 * 2 * 16 * 64 * 128];
__device__ unsigned g_barrier2[2];   // per-direction barrier counters

#define A_PD ((size_t)16 * 64 * 128)   // 131072 B per (parity,dir)

// smem: 16 chunks x (64 rows x 144B) = 147456; sred (64KB) + sh overlay it
#define SM_SH    90112
#define SM_TOTAL 147456

// ---------------------------------------------------------------------------
#define MMA16816(d, a0, a1, a2, a3, b0, b1)                                  \
    asm volatile(                                                            \
        "mma.sync.aligned.m16n8k16.row.col.f32.f16.f16.f32 "                 \
        "{%0,%1,%2,%3}, {%4,%5,%6,%7}, {%8,%9}, {%0,%1,%2,%3};"              \
        : "+f"((d)[0]), "+f"((d)[1]), "+f"((d)[2]), "+f"((d)[3])             \
        : "r"(a0), "r"(a1), "r"(a2), "r"(a3), "r"(b0), "r"(b1))

#define LDSM_X4(r0, r1, r2, r3, addr)                                        \
    asm volatile(                                                            \
        "ldmatrix.sync.aligned.m8n8.x4.shared.b16 {%0,%1,%2,%3}, [%4];"      \
        : "=r"(r0), "=r"(r1), "=r"(r2), "=r"(r3) : "r"(addr))

#define CP16(dst, src)                                                       \
    asm volatile("cp.async.cg.shared.global [%0], [%1], 16;"                 \
                 :: "r"(dst), "l"(src))

__device__ __forceinline__ uint32_t smem_u32(const void* p) {
    uint32_t a;
    asm("{ .reg .u64 t; cvta.to.shared.u64 t, %1; cvt.u32.u64 %0, t; }"
        : "=r"(a) : "l"(p));
    return a;
}

// ---------------------------------------------------------------------------
__global__ void init_kernel() {
    int i = blockIdx.x * blockDim.x + threadIdx.x;   // 0..131071
    ((uint32_t*)g_A)[i] = 0u;
    if (i < 2) g_barrier2[i] = 0u;
}

// ---------------------------------------------------------------------------
__global__ void convX_kernel(const float* __restrict__ X) {
    size_t idx = (size_t)blockIdx.x * blockDim.x + threadIdx.x;
    float4 v = ((const float4*)X)[idx];
    __half h0 = __float2half_rn(v.x), h1 = __float2half_rn(v.y);
    __half h2 = __float2half_rn(v.z), h3 = __float2half_rn(v.w);
    uint2 hi;
    hi.x = (uint32_t)__half_as_ushort(h0) | ((uint32_t)__half_as_ushort(h1) << 16);
    hi.y = (uint32_t)__half_as_ushort(h2) | ((uint32_t)__half_as_ushort(h3) << 16);
    ((uint2*)g_Xh)[idx] = hi;
}

// ---------------------------------------------------------------------------
__global__ void convW_kernel(const float* __restrict__ Whf,
                             const float* __restrict__ Whb) {
    int idx = blockIdx.x * blockDim.x + threadIdx.x;
    int lane = idx & 31;
    int kc   = (idx >> 5) & 63;
    int nt   = (idx >> 11) & 511;
    int dir  = idx >> 20;
    const float* W = dir ? Whb : Whf;

    int p   = nt * 8 + (lane >> 2);
    int col = ((p & 3) << 10) + (p >> 2);
    int k0  = kc * 16 + (lane & 3) * 2;

    float w0 = W[(size_t)(k0)     * GG + col];
    float w1 = W[(size_t)(k0 + 1) * GG + col];
    float w2 = W[(size_t)(k0 + 8) * GG + col];
    float w3 = W[(size_t)(k0 + 9) * GG + col];

    uint2 hi;
    hi.x = (uint32_t)__half_as_ushort(__float2half_rn(w0)) |
           ((uint32_t)__half_as_ushort(__float2half_rn(w1)) << 16);
    hi.y = (uint32_t)__half_as_ushort(__float2half_rn(w2)) |
           ((uint32_t)__half_as_ushort(__float2half_rn(w3)) << 16);

    g_Wfrag[(((size_t)dir * 512 + nt) * 64 + kc) * 32 + lane] = hi;
}

// ---------------------------------------------------------------------------
__global__ void convWx_kernel(const float* __restrict__ Wxf,
                              const float* __restrict__ Wxb,
                              const float* __restrict__ bf,
                              const float* __restrict__ bb) {
    int idx = blockIdx.x * blockDim.x + threadIdx.x;
    int lane = idx & 31;
    int kc   = (idx >> 5) & 31;
    int nt   = (idx >> 10) & 511;
    int dir  = idx >> 19;
    const float* W = dir ? Wxb : Wxf;

    int p   = nt * 8 + (lane >> 2);
    int col = ((p & 3) << 10) + (p >> 2);
    int k0  = kc * 16 + (lane & 3) * 2;

    float w0 = W[(size_t)(k0)     * GG + col];
    float w1 = W[(size_t)(k0 + 1) * GG + col];
    float w2 = W[(size_t)(k0 + 8) * GG + col];
    float w3 = W[(size_t)(k0 + 9) * GG + col];

    uint2 hi;
    hi.x = (uint32_t)__half_as_ushort(__float2half_rn(w0)) |
           ((uint32_t)__half_as_ushort(__float2half_rn(w1)) << 16);
    hi.y = (uint32_t)__half_as_ushort(__float2half_rn(w2)) |
           ((uint32_t)__half_as_ushort(__float2half_rn(w3)) << 16);

    g_Wxfrag[(((size_t)dir * 512 + nt) * 32 + kc) * 32 + lane] = hi;

    if (kc == 0 && (lane & 3) == 0) {
        const float* bias = dir ? bb : bf;
        g_biasp[dir * GG + p] = bias[col];
    }
}

// ---------------------------------------------------------------------------
// Input projection: 1-term fp16 mma (X_hi @ W_hi).  (unchanged)
// ---------------------------------------------------------------------------
__global__ void __launch_bounds__(256, 1) proj_kernel() {
    __shared__ __align__(16) char sX[2 * 6144];

    const int dir = blockIdx.z;
    const int n0 = blockIdx.x * 128;
    const int m0 = blockIdx.y * 128;
    const int tid = threadIdx.x;
    const int warp = tid >> 5, lane = tid & 31;
    const int wm = warp >> 2, wn = warp & 3;
    const int qr = lane >> 2, qc = lane & 3;

    const uint2* WX = g_Wxfrag + (size_t)dir * 512 * 32 * 32;
    const int ntbase = (n0 >> 3) + wn * 4;

    const uint32_t sX0 = smem_u32(sX);

    auto stage = [&](int c) {
        const int row = tid >> 1, q = tid & 1;
        const char* src = (const char*)g_Xh +
                          (((size_t)(m0 + row) * 512 + c * 16) << 1) + q * 16;
        const uint32_t dst = sX0 + (c & 1) * 6144 + row * 48 + q * 16;
        CP16(dst, src);
    };

    float d[4][4][4] = {};

    stage(0);
    asm volatile("cp.async.commit_group;" ::: "memory");

    for (int c = 0; c < 32; c++) {
        __syncthreads();
        if (c < 31) {
            stage(c + 1);
            asm volatile("cp.async.commit_group;" ::: "memory");
            asm volatile("cp.async.wait_group 1;" ::: "memory");
        } else {
            asm volatile("cp.async.wait_group 0;" ::: "memory");
        }
        __syncthreads();

        uint2 bh[4];
#pragma unroll
        for (int nt = 0; nt < 4; nt++)
            bh[nt] = WX[(((size_t)(ntbase + nt)) * 32 + c) * 32 + lane];

        const uint32_t slot = sX0 + (c & 1) * 6144;
        const uint32_t lrow = (lane & 15) * 48 + ((lane >> 4) << 4);
#pragma unroll
        for (int mt = 0; mt < 4; mt++) {
            const uint32_t arow = slot + (wm * 64 + mt * 16) * 48 + lrow;
            uint32_t a0, a1, a2, a3;
            LDSM_X4(a0, a1, a2, a3, arow);
#pragma unroll
            for (int nt = 0; nt < 4; nt++)
                MMA16816(d[mt][nt], a0, a1, a2, a3, bh[nt].x, bh[nt].y);
        }
    }

#pragma unroll
    for (int mt = 0; mt < 4; mt++) {
#pragma unroll
        for (int nt = 0; nt < 4; nt++) {
            const int n = n0 + wn * 32 + nt * 8 + qc * 2;
            const float2 bv = *(const float2*)(g_biasp + dir * GG + n);
            const int ma = m0 + wm * 64 + mt * 16 + qr;
            const int mb = ma + 8;
            float2 v0, v1;
            v0.x = d[mt][nt][0] + bv.x; v0.y = d[mt][nt][1] + bv.y;
            v1.x = d[mt][nt][2] + bv.x; v1.y = d[mt][nt][3] + bv.y;
            *(float2*)(g_xz + (((size_t)dir * TT + (ma & 511)) * BB + (ma >> 9)) * GG + n) = v0;
            *(float2*)(g_xz + (((size_t)dir * TT + (mb & 511)) * BB + (mb >> 9)) * GG + n) = v1;
        }
    }
}

// ---------------------------------------------------------------------------
// Persistent recurrence: grid (64,2), 512 threads = 4 ntw x 4 kh warps.
// W fragments are loop-invariant -> hoisted into 64 registers/thread before
// the step loop. Per-dir barrier counters. Other structure as R11.
// ---------------------------------------------------------------------------
__global__ void __launch_bounds__(512, 1) lstm_kernel(float* __restrict__ out) {
    extern __shared__ char dsm[];
    const uint32_t sA0 = smem_u32(dsm);               // 16 chunks x 64 x 144B
    float* sred = (float*)dsm;                        // overlays A (64KB)
    float (*sh)[17] = (float(*)[17])(dsm + SM_SH);    // [64][17] overlays A

    const int dir  = blockIdx.y;
    const int nblk = blockIdx.x;                      // 0..63
    const int tid  = threadIdx.x;
    const int warp = tid >> 5;
    const int lane = tid & 31;
    const int ntw = warp & 3;                         // 0..3: 2 ntiles each
    const int kh  = warp >> 2;                        // 0..3: 4 chunks each
    const int qr = lane >> 2;
    const int qc = lane & 3;
    const int ntg0 = nblk * 8 + ntw * 2;

    const int u = qc >> 1;
    const bool odd = qc & 1;
    const int mt = kh;                                // epilogue row tile
    const int bq = mt * 16 + qr + (odd ? 8 : 0);      // epilogue batch row

    const int st_b = tid >> 3;
    const int st_q = tid & 7;

    // ---- hoist this warp's W fragments into registers (loop-invariant) ----
    // wreg[nq][lc*4+sub] = kc16 index (kh*4+lc)*4+sub of ntile ntg0+nq
    uint2 wreg[2][16];
    {
        const uint2* Bh = g_Wfrag + (((size_t)dir * 512 + ntg0) * 64) * 32 + lane;
#pragma unroll
        for (int nq = 0; nq < 2; nq++)
#pragma unroll
            for (int i = 0; i < 16; i++)
                wreg[nq][i] = Bh[((size_t)nq * 64 + kh * 16 + i) * 32];
    }

    float cv[2] = {0.0f, 0.0f};

    float4 xv[2];
    {
        const int t0 = dir ? (TT - 1) : 0;
        const float* xz = g_xz + ((size_t)dir * TT + t0) * BB * GG;
#pragma unroll
        for (int q = 0; q < 2; q++) {
            const int jq = nblk * 16 + (ntw * 2 + q) * 2 + u;
            xv[q] = *(const float4*)(xz + (size_t)bq * GG + jq * 4);
        }
    }

    for (int s = 0; s < TT; s++) {
        const int t  = dir ? (TT - 1 - s) : s;
        const int pr = s & 1;
        const int pw = pr ^ 1;
        const char* srcA = g_A + (size_t)(pr * 2 + dir) * A_PD;

        // ---- stage all 16 chunks in 2 groups (group g: chunks bit1==g) ----
#pragma unroll
        for (int g = 0; g < 2; g++) {
#pragma unroll
            for (int ci = 0; ci < 8; ci++) {
                const int chunk = ((ci >> 1) << 2) | (g << 1) | (ci & 1);
                const char* src = srcA + (size_t)chunk * 8192 + st_b * 128 + st_q * 16;
                const uint32_t dst = sA0 + chunk * 9216 + st_b * 144 + st_q * 16;
                CP16(dst, src);
            }
            asm volatile("cp.async.commit_group;" ::: "memory");
        }

        float d[4][2][4] = {};

        // ---- compute: 2 phases x 2 chunks x 4 ksteps, 2 nt per A frag ----
#pragma unroll
        for (int phase = 0; phase < 2; phase++) {
            if (phase == 0) {
                asm volatile("cp.async.wait_group 1;" ::: "memory");
            } else {
                asm volatile("cp.async.wait_group 0;" ::: "memory");
            }
            __syncthreads();

#pragma unroll
            for (int cc = 0; cc < 2; cc++) {
                const int lc = phase * 2 + cc;        // local chunk 0..3
                const int chunk = kh * 4 + lc;
                const uint32_t slot = sA0 + chunk * 9216;
                const uint32_t lrow = (lane & 15) * 144 + ((lane >> 4) << 4);
#pragma unroll
                for (int sub = 0; sub < 4; sub++) {
                    const uint32_t arow = slot + sub * 32 + lrow;
                    const uint2 w0 = wreg[0][lc * 4 + sub];
                    const uint2 w1 = wreg[1][lc * 4 + sub];
#pragma unroll
                    for (int m = 0; m < 4; m++) {
                        uint32_t a0, a1, a2, a3;
                        LDSM_X4(a0, a1, a2, a3, arow + m * 2304);
                        MMA16816(d[m][0], a0, a1, a2, a3, w0.x, w0.y);
                        MMA16816(d[m][1], a0, a1, a2, a3, w1.x, w1.y);
                    }
                }
            }
        }

        // ---- 4-way k reduction via sred (overlays A; guard the WAR) ----
        __syncthreads();   // all LDSM reads of A region complete
        {
            const int wbase = (kh * 4 + ntw) * 1024;
#pragma unroll
            for (int m = 0; m < 4; m++)
#pragma unroll
                for (int nq = 0; nq < 2; nq++)
#pragma unroll
                    for (int e = 0; e < 4; e++)
                        sred[wbase + (m * 8 + nq * 4 + e) * 32 + lane] = d[m][nq][e];
        }
        __syncthreads();

        // ---- reduce + gate math: warp (ntw,kh) owns mt=kh, its 2 ntiles ----
        {
#pragma unroll
            for (int q = 0; q < 2; q++) {
                float z0 = d[mt][q][0], z1 = d[mt][q][1];
                float z2 = d[mt][q][2], z3 = d[mt][q][3];
#pragma unroll
                for (int src = 0; src < 4; src++) {
                    if (src == kh) continue;
                    const int rb = (src * 4 + ntw) * 1024 + (mt * 8 + q * 4) * 32 + lane;
                    z0 += sred[rb];
                    z1 += sred[rb + 32];
                    z2 += sred[rb + 64];
                    z3 += sred[rb + 96];
                }
                float e0 = __shfl_xor_sync(0xffffffffu, z0, 1);
                float e1 = __shfl_xor_sync(0xffffffffu, z1, 1);
                float e2 = __shfl_xor_sync(0xffffffffu, z2, 1);
                float e3 = __shfl_xor_sync(0xffffffffu, z3, 1);

                float zi = odd ? e2 : z0;
                float zf = odd ? e3 : z1;
                float zo = odd ? z2 : e0;
                float zg = odd ? z3 : e1;

                zi += xv[q].x; zf += xv[q].y; zo += xv[q].z; zg += xv[q].w;

                const float ig = 1.0f / (1.0f + __expf(-zi));
                const float fg = 1.0f / (1.0f + __expf(-zf));
                const float og = 1.0f / (1.0f + __expf(-zo));
                const float gt = tanhf(zg);

                const float cn = fg * cv[q] + ig * gt;
                const float hn = og * tanhf(cn);
                cv[q] = cn;
                sh[bq][(ntw * 2 + q) * 2 + u] = hn;
            }
        }
        __syncthreads();

        // ---- write h_hi (fp16) for next step, parity pw ----
        if (tid < 64) {
            const int b = tid;
            char* dst = g_A + (size_t)(pw * 2 + dir) * A_PD +
                        (size_t)(nblk >> 2) * 8192 + (size_t)b * 128 + (nblk & 3) * 32;
            __half tmp[16];
#pragma unroll
            for (int q = 0; q < 16; q++) tmp[q] = __float2half_rn(sh[b][q]);
            *(uint4*)(dst)      = *(uint4*)(tmp);
            *(uint4*)(dst + 16) = *(uint4*)(tmp + 8);
        }

        // ---- coalesced out store: 64B runs per (b, t) ----
        {
            const int b = tid >> 3;
            const int e = tid & 7;
            float2 v;
            v.x = sh[b][e * 2];
            v.y = sh[b][e * 2 + 1];
            *(float2*)(out + (((size_t)b * TT + t) * 2 + dir) * HH +
                       nblk * 16 + e * 2) = v;
        }

        // ---- per-dir grid barrier + next-step xz prefetch during spin ----
        if (s < TT - 1) {
            __syncthreads();
            if (tid == 0) {
                asm volatile("red.release.gpu.global.add.u32 [%0], 1;"
                             :: "l"(&g_barrier2[dir]) : "memory");
            }
            {
                const int tn = dir ? (TT - 2 - s) : (s + 1);
                const float* xz = g_xz + ((size_t)dir * TT + tn) * BB * GG;
#pragma unroll
                for (int q = 0; q < 2; q++) {
                    const int jq = nblk * 16 + (ntw * 2 + q) * 2 + u;
                    xv[q] = *(const float4*)(xz + (size_t)bq * GG + jq * 4);
                }
            }
            if (tid == 0) {
                const unsigned target = 64u * (unsigned)(s + 1);
                unsigned v;
                do {
                    asm volatile("ld.acquire.gpu.global.u32 %0, [%1];"
                                 : "=r"(v) : "l"(&g_barrier2[dir]) : "memory");
                } while (v < target);
            }
            __syncthreads();
        }
    }
}

// ---------------------------------------------------------------------------
extern "C" void kernel_launch(void* const* d_in, const int* in_sizes, int n_in,
                              void* d_out, int out_size) {
    const float* X    = (const float*)d_in[0];
    const float* Wx_f = (const float*)d_in[1];
    const float* Wh_f = (const float*)d_in[2];
    const float* b_f  = (const float*)d_in[3];
    const float* Wx_b = (const float*)d_in[4];
    const float* Wh_b = (const float*)d_in[5];
    const float* b_b  = (const float*)d_in[6];
    float* out = (float*)d_out;

    cudaFuncSetAttribute(lstm_kernel,
                         cudaFuncAttributeMaxDynamicSharedMemorySize, SM_TOTAL);

    init_kernel<<<512, 256>>>();
    convX_kernel<<<16384, 256>>>(X);
    convW_kernel<<<8192, 256>>>(Wh_f, Wh_b);
    convWx_kernel<<<4096, 256>>>(Wx_f, Wx_b, b_f, b_b);

    proj_kernel<<<dim3(32, 256, 2), 256>>>();

    lstm_kernel<<<dim3(64, 2), 512, SM_TOTAL>>>(out);
}

// round 13
// speedup vs baseline: 2.8672x; 1.0119x over previous
#include <cuda_runtime.h>
#include <cuda_fp16.h>
#include <math.h>
#include <stdint.h>

#define BB 64      // batch
#define TT 512     // seq len
#define DD 512     // input size
#define HH 1024    // hidden size
#define GG 4096    // 4*H

// ---------------------------------------------------------------------------
// Global scratch
// ---------------------------------------------------------------------------
// xz permuted fp16: [dir][t][b][p]
__device__ __half g_xz[(size_t)2 * TT * BB * GG];
// Wh fp16 (hi only), B-fragment order: [dir][nt(512)][kc16(64)][lane(32)]
__device__ uint2 g_Wfrag[(size_t)2 * 512 * 64 * 32];
// Wx fp16 (hi only), B-fragment order: [dir][nt(512)][kc16(32)][lane(32)]
__device__ uint2 g_Wxfrag[(size_t)2 * 512 * 32 * 32];
__device__ float g_biasp[2 * GG];
// X fp16 (hi only): [m(32768)][k(512)]
__device__ __half g_Xh[(size_t)32768 * 512];
// h fp16 (hi only): [parity][dir][kc64(16)][b(64)][64 halfs = 128B]
__device__ __align__(16) char g_A[(size_t)2 * 2 * 16 * 64 * 128];
__device__ unsigned g_barrier2[2];   // per-direction barrier counters

#define A_PD ((size_t)16 * 64 * 128)   // 131072 B per (parity,dir)

// smem: A 16 chunks x (64 x 144B) = 147456, then sred 64KB, then sh
#define SM_SRED  147456
#define SM_SH    (SM_SRED + 65536)        // 212992
#define SM_TOTAL (SM_SH + 64 * 17 * 4)    // 217344

// ---------------------------------------------------------------------------
#define MMA16816(d, a0, a1, a2, a3, b0, b1)                                  \
    asm volatile(                                                            \
        "mma.sync.aligned.m16n8k16.row.col.f32.f16.f16.f32 "                 \
        "{%0,%1,%2,%3}, {%4,%5,%6,%7}, {%8,%9}, {%0,%1,%2,%3};"              \
        : "+f"((d)[0]), "+f"((d)[1]), "+f"((d)[2]), "+f"((d)[3])             \
        : "r"(a0), "r"(a1), "r"(a2), "r"(a3), "r"(b0), "r"(b1))

#define LDSM_X4(r0, r1, r2, r3, addr)                                        \
    asm volatile(                                                            \
        "ldmatrix.sync.aligned.m8n8.x4.shared.b16 {%0,%1,%2,%3}, [%4];"      \
        : "=r"(r0), "=r"(r1), "=r"(r2), "=r"(r3) : "r"(addr))

#define CP16(dst, src)                                                       \
    asm volatile("cp.async.cg.shared.global [%0], [%1], 16;"                 \
                 :: "r"(dst), "l"(src))

__device__ __forceinline__ uint32_t smem_u32(const void* p) {
    uint32_t a;
    asm("{ .reg .u64 t; cvta.to.shared.u64 t, %1; cvt.u32.u64 %0, t; }"
        : "=r"(a) : "l"(p));
    return a;
}

// ---------------------------------------------------------------------------
__global__ void init_kernel() {
    int i = blockIdx.x * blockDim.x + threadIdx.x;   // 0..131071
    ((uint32_t*)g_A)[i] = 0u;
    if (i < 2) g_barrier2[i] = 0u;
}

// ---------------------------------------------------------------------------
__global__ void convX_kernel(const float* __restrict__ X) {
    size_t idx = (size_t)blockIdx.x * blockDim.x + threadIdx.x;
    float4 v = ((const float4*)X)[idx];
    __half h0 = __float2half_rn(v.x), h1 = __float2half_rn(v.y);
    __half h2 = __float2half_rn(v.z), h3 = __float2half_rn(v.w);
    uint2 hi;
    hi.x = (uint32_t)__half_as_ushort(h0) | ((uint32_t)__half_as_ushort(h1) << 16);
    hi.y = (uint32_t)__half_as_ushort(h2) | ((uint32_t)__half_as_ushort(h3) << 16);
    ((uint2*)g_Xh)[idx] = hi;
}

// ---------------------------------------------------------------------------
__global__ void convW_kernel(const float* __restrict__ Whf,
                             const float* __restrict__ Whb) {
    int idx = blockIdx.x * blockDim.x + threadIdx.x;
    int lane = idx & 31;
    int kc   = (idx >> 5) & 63;
    int nt   = (idx >> 11) & 511;
    int dir  = idx >> 20;
    const float* W = dir ? Whb : Whf;

    int p   = nt * 8 + (lane >> 2);
    int col = ((p & 3) << 10) + (p >> 2);
    int k0  = kc * 16 + (lane & 3) * 2;

    float w0 = W[(size_t)(k0)     * GG + col];
    float w1 = W[(size_t)(k0 + 1) * GG + col];
    float w2 = W[(size_t)(k0 + 8) * GG + col];
    float w3 = W[(size_t)(k0 + 9) * GG + col];

    uint2 hi;
    hi.x = (uint32_t)__half_as_ushort(__float2half_rn(w0)) |
           ((uint32_t)__half_as_ushort(__float2half_rn(w1)) << 16);
    hi.y = (uint32_t)__half_as_ushort(__float2half_rn(w2)) |
           ((uint32_t)__half_as_ushort(__float2half_rn(w3)) << 16);

    g_Wfrag[(((size_t)dir * 512 + nt) * 64 + kc) * 32 + lane] = hi;
}

// ---------------------------------------------------------------------------
__global__ void convWx_kernel(const float* __restrict__ Wxf,
                              const float* __restrict__ Wxb,
                              const float* __restrict__ bf,
                              const float* __restrict__ bb) {
    int idx = blockIdx.x * blockDim.x + threadIdx.x;
    int lane = idx & 31;
    int kc   = (idx >> 5) & 31;
    int nt   = (idx >> 10) & 511;
    int dir  = idx >> 19;
    const float* W = dir ? Wxb : Wxf;

    int p   = nt * 8 + (lane >> 2);
    int col = ((p & 3) << 10) + (p >> 2);
    int k0  = kc * 16 + (lane & 3) * 2;

    float w0 = W[(size_t)(k0)     * GG + col];
    float w1 = W[(size_t)(k0 + 1) * GG + col];
    float w2 = W[(size_t)(k0 + 8) * GG + col];
    float w3 = W[(size_t)(k0 + 9) * GG + col];

    uint2 hi;
    hi.x = (uint32_t)__half_as_ushort(__float2half_rn(w0)) |
           ((uint32_t)__half_as_ushort(__float2half_rn(w1)) << 16);
    hi.y = (uint32_t)__half_as_ushort(__float2half_rn(w2)) |
           ((uint32_t)__half_as_ushort(__float2half_rn(w3)) << 16);

    g_Wxfrag[(((size_t)dir * 512 + nt) * 32 + kc) * 32 + lane] = hi;

    if (kc == 0 && (lane & 3) == 0) {
        const float* bias = dir ? bb : bf;
        g_biasp[dir * GG + p] = bias[col];
    }
}

// ---------------------------------------------------------------------------
// Input projection: 1-term fp16 mma (X_hi @ W_hi); fp16 xz epilogue.
// ---------------------------------------------------------------------------
__global__ void __launch_bounds__(256, 1) proj_kernel() {
    __shared__ __align__(16) char sX[2 * 6144];

    const int dir = blockIdx.z;
    const int n0 = blockIdx.x * 128;
    const int m0 = blockIdx.y * 128;
    const int tid = threadIdx.x;
    const int warp = tid >> 5, lane = tid & 31;
    const int wm = warp >> 2, wn = warp & 3;
    const int qr = lane >> 2, qc = lane & 3;

    const uint2* WX = g_Wxfrag + (size_t)dir * 512 * 32 * 32;
    const int ntbase = (n0 >> 3) + wn * 4;

    const uint32_t sX0 = smem_u32(sX);

    auto stage = [&](int c) {
        const int row = tid >> 1, q = tid & 1;
        const char* src = (const char*)g_Xh +
                          (((size_t)(m0 + row) * 512 + c * 16) << 1) + q * 16;
        const uint32_t dst = sX0 + (c & 1) * 6144 + row * 48 + q * 16;
        CP16(dst, src);
    };

    float d[4][4][4] = {};

    stage(0);
    asm volatile("cp.async.commit_group;" ::: "memory");

    for (int c = 0; c < 32; c++) {
        __syncthreads();
        if (c < 31) {
            stage(c + 1);
            asm volatile("cp.async.commit_group;" ::: "memory");
            asm volatile("cp.async.wait_group 1;" ::: "memory");
        } else {
            asm volatile("cp.async.wait_group 0;" ::: "memory");
        }
        __syncthreads();

        uint2 bh[4];
#pragma unroll
        for (int nt = 0; nt < 4; nt++)
            bh[nt] = WX[(((size_t)(ntbase + nt)) * 32 + c) * 32 + lane];

        const uint32_t slot = sX0 + (c & 1) * 6144;
        const uint32_t lrow = (lane & 15) * 48 + ((lane >> 4) << 4);
#pragma unroll
        for (int mt = 0; mt < 4; mt++) {
            const uint32_t arow = slot + (wm * 64 + mt * 16) * 48 + lrow;
            uint32_t a0, a1, a2, a3;
            LDSM_X4(a0, a1, a2, a3, arow);
#pragma unroll
            for (int nt = 0; nt < 4; nt++)
                MMA16816(d[mt][nt], a0, a1, a2, a3, bh[nt].x, bh[nt].y);
        }
    }

#pragma unroll
    for (int mt = 0; mt < 4; mt++) {
#pragma unroll
        for (int nt = 0; nt < 4; nt++) {
            const int n = n0 + wn * 32 + nt * 8 + qc * 2;
            const float2 bv = *(const float2*)(g_biasp + dir * GG + n);
            const int ma = m0 + wm * 64 + mt * 16 + qr;
            const int mb = ma + 8;
            __half2 h0 = __floats2half2_rn(d[mt][nt][0] + bv.x, d[mt][nt][1] + bv.y);
            __half2 h1 = __floats2half2_rn(d[mt][nt][2] + bv.x, d[mt][nt][3] + bv.y);
            *(__half2*)(g_xz + (((size_t)dir * TT + (ma & 511)) * BB + (ma >> 9)) * GG + n) = h0;
            *(__half2*)(g_xz + (((size_t)dir * TT + (mb & 511)) * BB + (mb >> 9)) * GG + n) = h1;
        }
    }
}

// ---------------------------------------------------------------------------
// Persistent recurrence: grid (64,2), 512 threads = 4 ntw x 4 kh warps.
// W hoisted to registers; sred/sh in dedicated smem (no overlay, no WAR bar);
// fp16 xz; per-dir barrier.
// ---------------------------------------------------------------------------
__global__ void __launch_bounds__(512, 1) lstm_kernel(float* __restrict__ out) {
    extern __shared__ char dsm[];
    const uint32_t sA0 = smem_u32(dsm);               // 16 chunks x 64 x 144B
    float* sred = (float*)(dsm + SM_SRED);            // [4kh][4ntw][32][32]
    float (*sh)[17] = (float(*)[17])(dsm + SM_SH);    // [64][17]

    const int dir  = blockIdx.y;
    const int nblk = blockIdx.x;                      // 0..63
    const int tid  = threadIdx.x;
    const int warp = tid >> 5;
    const int lane = tid & 31;
    const int ntw = warp & 3;                         // 0..3: 2 ntiles each
    const int kh  = warp >> 2;                        // 0..3: 4 chunks each
    const int qr = lane >> 2;
    const int qc = lane & 3;
    const int ntg0 = nblk * 8 + ntw * 2;

    const int u = qc >> 1;
    const bool odd = qc & 1;
    const int mt = kh;                                // epilogue row tile
    const int bq = mt * 16 + qr + (odd ? 8 : 0);      // epilogue batch row

    const int st_b = tid >> 3;
    const int st_q = tid & 7;

    // ---- hoist this warp's W fragments into registers (loop-invariant) ----
    uint2 wreg[2][16];
    {
        const uint2* Bh = g_Wfrag + (((size_t)dir * 512 + ntg0) * 64) * 32 + lane;
#pragma unroll
        for (int nq = 0; nq < 2; nq++)
#pragma unroll
            for (int i = 0; i < 16; i++)
                wreg[nq][i] = Bh[((size_t)nq * 64 + kh * 16 + i) * 32];
    }

    float cv[2] = {0.0f, 0.0f};

    uint2 xv[2];
    {
        const int t0 = dir ? (TT - 1) : 0;
        const __half* xz = g_xz + ((size_t)dir * TT + t0) * BB * GG;
#pragma unroll
        for (int q = 0; q < 2; q++) {
            const int jq = nblk * 16 + (ntw * 2 + q) * 2 + u;
            xv[q] = *(const uint2*)(xz + (size_t)bq * GG + jq * 4);
        }
    }

    for (int s = 0; s < TT; s++) {
        const int t  = dir ? (TT - 1 - s) : s;
        const int pr = s & 1;
        const int pw = pr ^ 1;
        const char* srcA = g_A + (size_t)(pr * 2 + dir) * A_PD;

        // ---- stage all 16 chunks in 2 groups (group g: chunks bit1==g) ----
#pragma unroll
        for (int g = 0; g < 2; g++) {
#pragma unroll
            for (int ci = 0; ci < 8; ci++) {
                const int chunk = ((ci >> 1) << 2) | (g << 1) | (ci & 1);
                const char* src = srcA + (size_t)chunk * 8192 + st_b * 128 + st_q * 16;
                const uint32_t dst = sA0 + chunk * 9216 + st_b * 144 + st_q * 16;
                CP16(dst, src);
            }
            asm volatile("cp.async.commit_group;" ::: "memory");
        }

        float d[4][2][4] = {};

        // ---- compute: 2 phases x 2 chunks x 4 ksteps, 2 nt per A frag ----
#pragma unroll
        for (int phase = 0; phase < 2; phase++) {
            if (phase == 0) {
                asm volatile("cp.async.wait_group 1;" ::: "memory");
            } else {
                asm volatile("cp.async.wait_group 0;" ::: "memory");
            }
            __syncthreads();

#pragma unroll
            for (int cc = 0; cc < 2; cc++) {
                const int lc = phase * 2 + cc;        // local chunk 0..3
                const int chunk = kh * 4 + lc;
                const uint32_t slot = sA0 + chunk * 9216;
                const uint32_t lrow = (lane & 15) * 144 + ((lane >> 4) << 4);
#pragma unroll
                for (int sub = 0; sub < 4; sub++) {
                    const uint32_t arow = slot + sub * 32 + lrow;
                    const uint2 w0 = wreg[0][lc * 4 + sub];
                    const uint2 w1 = wreg[1][lc * 4 + sub];
#pragma unroll
                    for (int m = 0; m < 4; m++) {
                        uint32_t a0, a1, a2, a3;
                        LDSM_X4(a0, a1, a2, a3, arow + m * 2304);
                        MMA16816(d[m][0], a0, a1, a2, a3, w0.x, w0.y);
                        MMA16816(d[m][1], a0, a1, a2, a3, w1.x, w1.y);
                    }
                }
            }
        }

        // ---- export partials (dedicated sred; no WAR hazard, no extra bar) ----
        {
            const int wbase = (kh * 4 + ntw) * 1024;
#pragma unroll
            for (int m = 0; m < 4; m++)
#pragma unroll
                for (int nq = 0; nq < 2; nq++)
#pragma unroll
                    for (int e = 0; e < 4; e++)
                        sred[wbase + (m * 8 + nq * 4 + e) * 32 + lane] = d[m][nq][e];
        }
        __syncthreads();

        // ---- reduce + gate math: warp (ntw,kh) owns mt=kh, its 2 ntiles ----
        {
#pragma unroll
            for (int q = 0; q < 2; q++) {
                float z0 = d[mt][q][0], z1 = d[mt][q][1];
                float z2 = d[mt][q][2], z3 = d[mt][q][3];
#pragma unroll
                for (int src = 0; src < 4; src++) {
                    if (src == kh) continue;
                    const int rb = (src * 4 + ntw) * 1024 + (mt * 8 + q * 4) * 32 + lane;
                    z0 += sred[rb];
                    z1 += sred[rb + 32];
                    z2 += sred[rb + 64];
                    z3 += sred[rb + 96];
                }
                float e0 = __shfl_xor_sync(0xffffffffu, z0, 1);
                float e1 = __shfl_xor_sync(0xffffffffu, z1, 1);
                float e2 = __shfl_xor_sync(0xffffffffu, z2, 1);
                float e3 = __shfl_xor_sync(0xffffffffu, z3, 1);

                float zi = odd ? e2 : z0;
                float zf = odd ? e3 : z1;
                float zo = odd ? z2 : e0;
                float zg = odd ? z3 : e1;

                const float2 x01 = __half22float2(*(const __half2*)&xv[q].x);
                const float2 x23 = __half22float2(*(const __half2*)&xv[q].y);
                zi += x01.x; zf += x01.y; zo += x23.x; zg += x23.y;

                const float ig = 1.0f / (1.0f + __expf(-zi));
                const float fg = 1.0f / (1.0f + __expf(-zf));
                const float og = 1.0f / (1.0f + __expf(-zo));
                const float gt = tanhf(zg);

                const float cn = fg * cv[q] + ig * gt;
                const float hn = og * tanhf(cn);
                cv[q] = cn;
                sh[bq][(ntw * 2 + q) * 2 + u] = hn;
            }
        }
        __syncthreads();

        // ---- write h_hi (fp16) for next step, parity pw ----
        if (tid < 64) {
            const int b = tid;
            char* dst = g_A + (size_t)(pw * 2 + dir) * A_PD +
                        (size_t)(nblk >> 2) * 8192 + (size_t)b * 128 + (nblk & 3) * 32;
            __half tmp[16];
#pragma unroll
            for (int q = 0; q < 16; q++) tmp[q] = __float2half_rn(sh[b][q]);
            *(uint4*)(dst)      = *(uint4*)(tmp);
            *(uint4*)(dst + 16) = *(uint4*)(tmp + 8);
        }

        // ---- coalesced out store: 64B runs per (b, t) ----
        {
            const int b = tid >> 3;
            const int e = tid & 7;
            float2 v;
            v.x = sh[b][e * 2];
            v.y = sh[b][e * 2 + 1];
            *(float2*)(out + (((size_t)b * TT + t) * 2 + dir) * HH +
                       nblk * 16 + e * 2) = v;
        }

        // ---- per-dir grid barrier + next-step xz prefetch during spin ----
        if (s < TT - 1) {
            __syncthreads();
            if (tid == 0) {
                asm volatile("red.release.gpu.global.add.u32 [%0], 1;"
                             :: "l"(&g_barrier2[dir]) : "memory");
            }
            {
                const int tn = dir ? (TT - 2 - s) : (s + 1);
                const __half* xz = g_xz + ((size_t)dir * TT + tn) * BB * GG;
#pragma unroll
                for (int q = 0; q < 2; q++) {
                    const int jq = nblk * 16 + (ntw * 2 + q) * 2 + u;
                    xv[q] = *(const uint2*)(xz + (size_t)bq * GG + jq * 4);
                }
            }
            if (tid == 0) {
                const unsigned target = 64u * (unsigned)(s + 1);
                unsigned v;
                do {
                    asm volatile("ld.acquire.gpu.global.u32 %0, [%1];"
                                 : "=r"(v) : "l"(&g_barrier2[dir]) : "memory");
                } while (v < target);
            }
            __syncthreads();
        }
    }
}

// ---------------------------------------------------------------------------
extern "C" void kernel_launch(void* const* d_in, const int* in_sizes, int n_in,
                              void* d_out, int out_size) {
    const float* X    = (const float*)d_in[0];
    const float* Wx_f = (const float*)d_in[1];
    const float* Wh_f = (const float*)d_in[2];
    const float* b_f  = (const float*)d_in[3];
    const float* Wx_b = (const float*)d_in[4];
    const float* Wh_b = (const float*)d_in[5];
    const float* b_b  = (const float*)d_in[6];
    float* out = (float*)d_out;

    cudaFuncSetAttribute(lstm_kernel,
                         cudaFuncAttributeMaxDynamicSharedMemorySize, SM_TOTAL);

    init_kernel<<<512, 256>>>();
    convX_kernel<<<16384, 256>>>(X);
    convW_kernel<<<8192, 256>>>(Wh_f, Wh_b);
    convWx_kernel<<<4096, 256>>>(Wx_f, Wx_b, b_f, b_b);

    proj_kernel<<<dim3(32, 256, 2), 256>>>();

    lstm_kernel<<<dim3(64, 2), 512, SM_TOTAL>>>(out);
}

// round 14
// speedup vs baseline: 2.9288x; 1.0215x over previous
#include <cuda_runtime.h>
#include <cuda_fp16.h>
#include <math.h>
#include <stdint.h>

#define BB 64      // batch
#define TT 512     // seq len
#define DD 512     // input size
#define HH 1024    // hidden size
#define GG 4096    // 4*H

// ---------------------------------------------------------------------------
// Global scratch
// ---------------------------------------------------------------------------
// xz permuted fp16: [dir][t][b][p]
__device__ __half g_xz[(size_t)2 * TT * BB * GG];
// Wh fp16 (hi only), B-fragment order: [dir][nt(512)][kc16(64)][lane(32)]
__device__ uint2 g_Wfrag[(size_t)2 * 512 * 64 * 32];
// Wx fp16 (hi only), B-fragment order: [dir][nt(512)][kc16(32)][lane(32)]
__device__ uint2 g_Wxfrag[(size_t)2 * 512 * 32 * 32];
__device__ float g_biasp[2 * GG];
// X fp16 (hi only): [m(32768)][k(512)]
__device__ __half g_Xh[(size_t)32768 * 512];
// h fp16 (hi only): [parity][dir][kc64(16)][b(64)][64 halfs = 128B]
__device__ __align__(16) char g_A[(size_t)2 * 2 * 16 * 64 * 128];
__device__ unsigned g_barrier2[2];   // per-direction barrier counters

#define A_PD ((size_t)16 * 64 * 128)   // 131072 B per (parity,dir)

// smem: A 16 chunks x (64 x 144B) = 147456, then sred 64KB, then sh
#define SM_SRED  147456
#define SM_SH    (SM_SRED + 65536)        // 212992
#define SM_TOTAL (SM_SH + 64 * 17 * 4)    // 217344

// ---------------------------------------------------------------------------
#define MMA16816(d, a0, a1, a2, a3, b0, b1)                                  \
    asm volatile(                                                            \
        "mma.sync.aligned.m16n8k16.row.col.f32.f16.f16.f32 "                 \
        "{%0,%1,%2,%3}, {%4,%5,%6,%7}, {%8,%9}, {%0,%1,%2,%3};"              \
        : "+f"((d)[0]), "+f"((d)[1]), "+f"((d)[2]), "+f"((d)[3])             \
        : "r"(a0), "r"(a1), "r"(a2), "r"(a3), "r"(b0), "r"(b1))

#define LDSM_X4(r0, r1, r2, r3, addr)                                        \
    asm volatile(                                                            \
        "ldmatrix.sync.aligned.m8n8.x4.shared.b16 {%0,%1,%2,%3}, [%4];"      \
        : "=r"(r0), "=r"(r1), "=r"(r2), "=r"(r3) : "r"(addr))

#define CP16(dst, src)                                                       \
    asm volatile("cp.async.cg.shared.global [%0], [%1], 16;"                 \
                 :: "r"(dst), "l"(src))

__device__ __forceinline__ uint32_t smem_u32(const void* p) {
    uint32_t a;
    asm("{ .reg .u64 t; cvta.to.shared.u64 t, %1; cvt.u32.u64 %0, t; }"
        : "=r"(a) : "l"(p));
    return a;
}

__device__ __forceinline__ float tanh_fast(float x) {
    float y;
    asm("tanh.approx.f32 %0, %1;" : "=f"(y) : "f"(x));
    return y;
}
__device__ __forceinline__ float sigmoid_fast(float x) {
    return fmaf(tanh_fast(0.5f * x), 0.5f, 0.5f);
}

// ---------------------------------------------------------------------------
__global__ void init_kernel() {
    int i = blockIdx.x * blockDim.x + threadIdx.x;   // 0..131071
    ((uint32_t*)g_A)[i] = 0u;
    if (i < 2) g_barrier2[i] = 0u;
}

// ---------------------------------------------------------------------------
__global__ void convX_kernel(const float* __restrict__ X) {
    size_t idx = (size_t)blockIdx.x * blockDim.x + threadIdx.x;
    float4 v = ((const float4*)X)[idx];
    __half h0 = __float2half_rn(v.x), h1 = __float2half_rn(v.y);
    __half h2 = __float2half_rn(v.z), h3 = __float2half_rn(v.w);
    uint2 hi;
    hi.x = (uint32_t)__half_as_ushort(h0) | ((uint32_t)__half_as_ushort(h1) << 16);
    hi.y = (uint32_t)__half_as_ushort(h2) | ((uint32_t)__half_as_ushort(h3) << 16);
    ((uint2*)g_Xh)[idx] = hi;
}

// ---------------------------------------------------------------------------
__global__ void convW_kernel(const float* __restrict__ Whf,
                             const float* __restrict__ Whb) {
    int idx = blockIdx.x * blockDim.x + threadIdx.x;
    int lane = idx & 31;
    int kc   = (idx >> 5) & 63;
    int nt   = (idx >> 11) & 511;
    int dir  = idx >> 20;
    const float* W = dir ? Whb : Whf;

    int p   = nt * 8 + (lane >> 2);
    int col = ((p & 3) << 10) + (p >> 2);
    int k0  = kc * 16 + (lane & 3) * 2;

    float w0 = W[(size_t)(k0)     * GG + col];
    float w1 = W[(size_t)(k0 + 1) * GG + col];
    float w2 = W[(size_t)(k0 + 8) * GG + col];
    float w3 = W[(size_t)(k0 + 9) * GG + col];

    uint2 hi;
    hi.x = (uint32_t)__half_as_ushort(__float2half_rn(w0)) |
           ((uint32_t)__half_as_ushort(__float2half_rn(w1)) << 16);
    hi.y = (uint32_t)__half_as_ushort(__float2half_rn(w2)) |
           ((uint32_t)__half_as_ushort(__float2half_rn(w3)) << 16);

    g_Wfrag[(((size_t)dir * 512 + nt) * 64 + kc) * 32 + lane] = hi;
}

// ---------------------------------------------------------------------------
__global__ void convWx_kernel(const float* __restrict__ Wxf,
                              const float* __restrict__ Wxb,
                              const float* __restrict__ bf,
                              const float* __restrict__ bb) {
    int idx = blockIdx.x * blockDim.x + threadIdx.x;
    int lane = idx & 31;
    int kc   = (idx >> 5) & 31;
    int nt   = (idx >> 10) & 511;
    int dir  = idx >> 19;
    const float* W = dir ? Wxb : Wxf;

    int p   = nt * 8 + (lane >> 2);
    int col = ((p & 3) << 10) + (p >> 2);
    int k0  = kc * 16 + (lane & 3) * 2;

    float w0 = W[(size_t)(k0)     * GG + col];
    float w1 = W[(size_t)(k0 + 1) * GG + col];
    float w2 = W[(size_t)(k0 + 8) * GG + col];
    float w3 = W[(size_t)(k0 + 9) * GG + col];

    uint2 hi;
    hi.x = (uint32_t)__half_as_ushort(__float2half_rn(w0)) |
           ((uint32_t)__half_as_ushort(__float2half_rn(w1)) << 16);
    hi.y = (uint32_t)__half_as_ushort(__float2half_rn(w2)) |
           ((uint32_t)__half_as_ushort(__float2half_rn(w3)) << 16);

    g_Wxfrag[(((size_t)dir * 512 + nt) * 32 + kc) * 32 + lane] = hi;

    if (kc == 0 && (lane & 3) == 0) {
        const float* bias = dir ? bb : bf;
        g_biasp[dir * GG + p] = bias[col];
    }
}

// ---------------------------------------------------------------------------
// Input projection: 1-term fp16 mma (X_hi @ W_hi); fp16 xz epilogue.
// ---------------------------------------------------------------------------
__global__ void __launch_bounds__(256, 1) proj_kernel() {
    __shared__ __align__(16) char sX[2 * 6144];

    const int dir = blockIdx.z;
    const int n0 = blockIdx.x * 128;
    const int m0 = blockIdx.y * 128;
    const int tid = threadIdx.x;
    const int warp = tid >> 5, lane = tid & 31;
    const int wm = warp >> 2, wn = warp & 3;
    const int qr = lane >> 2, qc = lane & 3;

    const uint2* WX = g_Wxfrag + (size_t)dir * 512 * 32 * 32;
    const int ntbase = (n0 >> 3) + wn * 4;

    const uint32_t sX0 = smem_u32(sX);

    auto stage = [&](int c) {
        const int row = tid >> 1, q = tid & 1;
        const char* src = (const char*)g_Xh +
                          (((size_t)(m0 + row) * 512 + c * 16) << 1) + q * 16;
        const uint32_t dst = sX0 + (c & 1) * 6144 + row * 48 + q * 16;
        CP16(dst, src);
    };

    float d[4][4][4] = {};

    stage(0);
    asm volatile("cp.async.commit_group;" ::: "memory");

    for (int c = 0; c < 32; c++) {
        __syncthreads();
        if (c < 31) {
            stage(c + 1);
            asm volatile("cp.async.commit_group;" ::: "memory");
            asm volatile("cp.async.wait_group 1;" ::: "memory");
        } else {
            asm volatile("cp.async.wait_group 0;" ::: "memory");
        }
        __syncthreads();

        uint2 bh[4];
#pragma unroll
        for (int nt = 0; nt < 4; nt++)
            bh[nt] = WX[(((size_t)(ntbase + nt)) * 32 + c) * 32 + lane];

        const uint32_t slot = sX0 + (c & 1) * 6144;
        const uint32_t lrow = (lane & 15) * 48 + ((lane >> 4) << 4);
#pragma unroll
        for (int mt = 0; mt < 4; mt++) {
            const uint32_t arow = slot + (wm * 64 + mt * 16) * 48 + lrow;
            uint32_t a0, a1, a2, a3;
            LDSM_X4(a0, a1, a2, a3, arow);
#pragma unroll
            for (int nt = 0; nt < 4; nt++)
                MMA16816(d[mt][nt], a0, a1, a2, a3, bh[nt].x, bh[nt].y);
        }
    }

#pragma unroll
    for (int mt = 0; mt < 4; mt++) {
#pragma unroll
        for (int nt = 0; nt < 4; nt++) {
            const int n = n0 + wn * 32 + nt * 8 + qc * 2;
            const float2 bv = *(const float2*)(g_biasp + dir * GG + n);
            const int ma = m0 + wm * 64 + mt * 16 + qr;
            const int mb = ma + 8;
            __half2 h0 = __floats2half2_rn(d[mt][nt][0] + bv.x, d[mt][nt][1] + bv.y);
            __half2 h1 = __floats2half2_rn(d[mt][nt][2] + bv.x, d[mt][nt][3] + bv.y);
            *(__half2*)(g_xz + (((size_t)dir * TT + (ma & 511)) * BB + (ma >> 9)) * GG + n) = h0;
            *(__half2*)(g_xz + (((size_t)dir * TT + (mb & 511)) * BB + (mb >> 9)) * GG + n) = h1;
        }
    }
}

// ---------------------------------------------------------------------------
// Persistent recurrence: grid (64,2), 512 threads = 4 ntw x 4 kh warps.
// W in registers; MUFU-based gate math; out store overlapped with barrier spin.
// ---------------------------------------------------------------------------
__global__ void __launch_bounds__(512, 1) lstm_kernel(float* __restrict__ out) {
    extern __shared__ char dsm[];
    const uint32_t sA0 = smem_u32(dsm);               // 16 chunks x 64 x 144B
    float* sred = (float*)(dsm + SM_SRED);            // [4kh][4ntw][32][32]
    float (*sh)[17] = (float(*)[17])(dsm + SM_SH);    // [64][17]

    const int dir  = blockIdx.y;
    const int nblk = blockIdx.x;                      // 0..63
    const int tid  = threadIdx.x;
    const int warp = tid >> 5;
    const int lane = tid & 31;
    const int ntw = warp & 3;                         // 0..3: 2 ntiles each
    const int kh  = warp >> 2;                        // 0..3: 4 chunks each
    const int qr = lane >> 2;
    const int qc = lane & 3;
    const int ntg0 = nblk * 8 + ntw * 2;

    const int u = qc >> 1;
    const bool odd = qc & 1;
    const int mt = kh;                                // epilogue row tile
    const int bq = mt * 16 + qr + (odd ? 8 : 0);      // epilogue batch row

    const int st_b = tid >> 3;
    const int st_q = tid & 7;

    // ---- hoist this warp's W fragments into registers (loop-invariant) ----
    uint2 wreg[2][16];
    {
        const uint2* Bh = g_Wfrag + (((size_t)dir * 512 + ntg0) * 64) * 32 + lane;
#pragma unroll
        for (int nq = 0; nq < 2; nq++)
#pragma unroll
            for (int i = 0; i < 16; i++)
                wreg[nq][i] = Bh[((size_t)nq * 64 + kh * 16 + i) * 32];
    }

    float cv[2] = {0.0f, 0.0f};

    uint2 xv[2];
    {
        const int t0 = dir ? (TT - 1) : 0;
        const __half* xz = g_xz + ((size_t)dir * TT + t0) * BB * GG;
#pragma unroll
        for (int q = 0; q < 2; q++) {
            const int jq = nblk * 16 + (ntw * 2 + q) * 2 + u;
            xv[q] = *(const uint2*)(xz + (size_t)bq * GG + jq * 4);
        }
    }

    for (int s = 0; s < TT; s++) {
        const int t  = dir ? (TT - 1 - s) : s;
        const int pr = s & 1;
        const int pw = pr ^ 1;
        const char* srcA = g_A + (size_t)(pr * 2 + dir) * A_PD;

        // ---- stage all 16 chunks in 2 groups (group g: chunks bit1==g) ----
#pragma unroll
        for (int g = 0; g < 2; g++) {
#pragma unroll
            for (int ci = 0; ci < 8; ci++) {
                const int chunk = ((ci >> 1) << 2) | (g << 1) | (ci & 1);
                const char* src = srcA + (size_t)chunk * 8192 + st_b * 128 + st_q * 16;
                const uint32_t dst = sA0 + chunk * 9216 + st_b * 144 + st_q * 16;
                CP16(dst, src);
            }
            asm volatile("cp.async.commit_group;" ::: "memory");
        }

        float d[4][2][4] = {};

        // ---- compute: 2 phases x 2 chunks x 4 ksteps, 2 nt per A frag ----
#pragma unroll
        for (int phase = 0; phase < 2; phase++) {
            if (phase == 0) {
                asm volatile("cp.async.wait_group 1;" ::: "memory");
            } else {
                asm volatile("cp.async.wait_group 0;" ::: "memory");
            }
            __syncthreads();

#pragma unroll
            for (int cc = 0; cc < 2; cc++) {
                const int lc = phase * 2 + cc;        // local chunk 0..3
                const int chunk = kh * 4 + lc;
                const uint32_t slot = sA0 + chunk * 9216;
                const uint32_t lrow = (lane & 15) * 144 + ((lane >> 4) << 4);
#pragma unroll
                for (int sub = 0; sub < 4; sub++) {
                    const uint32_t arow = slot + sub * 32 + lrow;
                    const uint2 w0 = wreg[0][lc * 4 + sub];
                    const uint2 w1 = wreg[1][lc * 4 + sub];
#pragma unroll
                    for (int m = 0; m < 4; m++) {
                        uint32_t a0, a1, a2, a3;
                        LDSM_X4(a0, a1, a2, a3, arow + m * 2304);
                        MMA16816(d[m][0], a0, a1, a2, a3, w0.x, w0.y);
                        MMA16816(d[m][1], a0, a1, a2, a3, w1.x, w1.y);
                    }
                }
            }
        }

        // ---- export partials for the 3 non-owned mt tiles ----
        {
            const int wbase = (kh * 4 + ntw) * 1024;
#pragma unroll
            for (int m = 0; m < 4; m++) {
                if (m == kh) continue;
#pragma unroll
                for (int nq = 0; nq < 2; nq++)
#pragma unroll
                    for (int e = 0; e < 4; e++)
                        sred[wbase + (m * 8 + nq * 4 + e) * 32 + lane] = d[m][nq][e];
            }
        }
        __syncthreads();

        // ---- reduce + gate math: warp (ntw,kh) owns mt=kh, its 2 ntiles ----
        {
#pragma unroll
            for (int q = 0; q < 2; q++) {
                float z0 = d[mt][q][0], z1 = d[mt][q][1];
                float z2 = d[mt][q][2], z3 = d[mt][q][3];
#pragma unroll
                for (int src = 0; src < 4; src++) {
                    if (src == kh) continue;
                    const int rb = (src * 4 + ntw) * 1024 + (mt * 8 + q * 4) * 32 + lane;
                    z0 += sred[rb];
                    z1 += sred[rb + 32];
                    z2 += sred[rb + 64];
                    z3 += sred[rb + 96];
                }
                float e0 = __shfl_xor_sync(0xffffffffu, z0, 1);
                float e1 = __shfl_xor_sync(0xffffffffu, z1, 1);
                float e2 = __shfl_xor_sync(0xffffffffu, z2, 1);
                float e3 = __shfl_xor_sync(0xffffffffu, z3, 1);

                float zi = odd ? e2 : z0;
                float zf = odd ? e3 : z1;
                float zo = odd ? z2 : e0;
                float zg = odd ? z3 : e1;

                const float2 x01 = __half22float2(*(const __half2*)&xv[q].x);
                const float2 x23 = __half22float2(*(const __half2*)&xv[q].y);
                zi += x01.x; zf += x01.y; zo += x23.x; zg += x23.y;

                const float ig = sigmoid_fast(zi);
                const float fg = sigmoid_fast(zf);
                const float og = sigmoid_fast(zo);
                const float gt = tanh_fast(zg);

                const float cn = fg * cv[q] + ig * gt;
                const float hn = og * tanh_fast(cn);
                cv[q] = cn;
                sh[bq][(ntw * 2 + q) * 2 + u] = hn;
            }
        }
        __syncthreads();

        // ---- write h_hi (fp16) for next step, parity pw ----
        if (tid < 64) {
            const int b = tid;
            char* dst = g_A + (size_t)(pw * 2 + dir) * A_PD +
                        (size_t)(nblk >> 2) * 8192 + (size_t)b * 128 + (nblk & 3) * 32;
            __half tmp[16];
#pragma unroll
            for (int q = 0; q < 16; q++) tmp[q] = __float2half_rn(sh[b][q]);
            *(uint4*)(dst)      = *(uint4*)(tmp);
            *(uint4*)(dst + 16) = *(uint4*)(tmp + 8);
        }

        // ---- out store (reads sh): overlapped with barrier spin below ----
        auto store_out = [&]() {
            const int b = tid >> 3;
            const int e = tid & 7;
            float2 v;
            v.x = sh[b][e * 2];
            v.y = sh[b][e * 2 + 1];
            *(float2*)(out + (((size_t)b * TT + t) * 2 + dir) * HH +
                       nblk * 16 + e * 2) = v;
        };

        if (s < TT - 1) {
            __syncthreads();   // h-write visible CTA-wide before arrive
            if (tid == 0) {
                asm volatile("red.release.gpu.global.add.u32 [%0], 1;"
                             :: "l"(&g_barrier2[dir]) : "memory");
            }
            store_out();       // overlap with spin
            {
                const int tn = dir ? (TT - 2 - s) : (s + 1);
                const __half* xz = g_xz + ((size_t)dir * TT + tn) * BB * GG;
#pragma unroll
                for (int q = 0; q < 2; q++) {
                    const int jq = nblk * 16 + (ntw * 2 + q) * 2 + u;
                    xv[q] = *(const uint2*)(xz + (size_t)bq * GG + jq * 4);
                }
            }
            if (tid == 0) {
                const unsigned target = 64u * (unsigned)(s + 1);
                unsigned v;
                do {
                    asm volatile("ld.acquire.gpu.global.u32 %0, [%1];"
                                 : "=r"(v) : "l"(&g_barrier2[dir]) : "memory");
                } while (v < target);
            }
            __syncthreads();
        } else {
            store_out();
        }
    }
}

// ---------------------------------------------------------------------------
extern "C" void kernel_launch(void* const* d_in, const int* in_sizes, int n_in,
                              void* d_out, int out_size) {
    const float* X    = (const float*)d_in[0];
    const float* Wx_f = (const float*)d_in[1];
    const float* Wh_f = (const float*)d_in[2];
    const float* b_f  = (const float*)d_in[3];
    const float* Wx_b = (const float*)d_in[4];
    const float* Wh_b = (const float*)d_in[5];
    const float* b_b  = (const float*)d_in[6];
    float* out = (float*)d_out;

    cudaFuncSetAttribute(lstm_kernel,
                         cudaFuncAttributeMaxDynamicSharedMemorySize, SM_TOTAL);

    init_kernel<<<512, 256>>>();
    convX_kernel<<<16384, 256>>>(X);
    convW_kernel<<<8192, 256>>>(Wh_f, Wh_b);
    convWx_kernel<<<4096, 256>>>(Wx_f, Wx_b, b_f, b_b);

    proj_kernel<<<dim3(32, 256, 2), 256>>>();

    lstm_kernel<<<dim3(64, 2), 512, SM_TOTAL>>>(out);
}